// round 12
// baseline (speedup 1.0000x reference)
#include <cuda_runtime.h>
#include <cuda_bf16.h>
#include <cstdint>
#include <math.h>

#define B_   64
#define T_   256
#define E_   300
#define EP_  320
#define H_   512
#define D_   1024
#define G_   2048
#define OUT_ 256
#define NB_LSTM 128u
#define BT_  (B_*T_)

// ---------------- fp32 scratch ----------------
__device__ float g_embeds[BT_*E_];
__device__ float g_xpre_f[BT_*G_];
__device__ float g_xpre_b[BT_*G_];
__device__ float g_ctx[BT_*D_];
__device__ float g_scores[BT_*T_];
__device__ float g_htilde[BT_*D_];
__device__ float g_ctxout[B_*D_];
__device__ float g_y[B_*OUT_];
__device__ float g_bsum_f[G_];
__device__ float g_bsum_b[G_];
__device__ volatile unsigned g_flags[NB_LSTM * 8];   // 32B-padded per-block barrier flags

// LSTM recurrent h, split bf16, double-buffered: [dir][buf][64*512]
__device__ __align__(16) __nv_bfloat16 g_hhi[2][2][B_*H_];
__device__ __align__(16) __nv_bfloat16 g_hlo[2][2][B_*H_];

// ---------------- bf16 hi/lo scratch (16B aligned) ----------------
__device__ __align__(16) __nv_bfloat16 g_eh[BT_*EP_],   g_el[BT_*EP_];
__device__ __align__(16) __nv_bfloat16 g_wfh[G_*EP_],   g_wfl[G_*EP_];
__device__ __align__(16) __nv_bfloat16 g_wbh[G_*EP_],   g_wbl[G_*EP_];
__device__ __align__(16) __nv_bfloat16 g_ch[BT_*D_],    g_cl[BT_*D_];
__device__ __align__(16) __nv_bfloat16 g_cth[B_*D_*T_], g_ctl[B_*D_*T_];
__device__ __align__(16) __nv_bfloat16 g_winh[D_*D_],   g_winl[D_*D_];
__device__ __align__(16) __nv_bfloat16 g_th[BT_*D_],    g_tl[BT_*D_];
__device__ __align__(16) __nv_bfloat16 g_ah[BT_*T_],    g_al[BT_*T_];
__device__ __align__(16) __nv_bfloat16 g_w1h[D_*D_],    g_w1l[D_*D_];
__device__ __align__(16) __nv_bfloat16 g_w2h[D_*D_],    g_w2l[D_*D_];
__device__ __align__(16) __nv_bfloat16 g_wh[BT_*D_],    g_wl[BT_*D_];

// ---------------- embedding ----------------
__global__ void embed_kernel(const int* __restrict__ inp, const float* __restrict__ table) {
    int idx = blockIdx.x * blockDim.x + threadIdx.x;
    if (idx >= BT_*E_) return;
    int bt = idx / E_, e = idx - bt * E_;
    g_embeds[idx] = table[(long)inp[bt] * E_ + e];
}

// ---------------- fp32 -> bf16 hi/lo split (with K pad) ----------------
__global__ void conv_kernel(const float* __restrict__ src, __nv_bfloat16* __restrict__ hi,
                            __nv_bfloat16* __restrict__ lo, int rows, int scols, int sld, int dld) {
    long idx = (long)blockIdx.x * 256 + threadIdx.x;
    if (idx >= (long)rows * dld) return;
    int r = idx / dld, c = idx - (long)r * dld;
    float v = (c < scols) ? src[(long)r * sld + c] : 0.f;
    __nv_bfloat16 h = __float2bfloat16(v);
    hi[idx] = h;
    lo[idx] = __float2bfloat16(v - __bfloat162float(h));
}

// ---------------- ctx transpose + split: [b][t][d] -> [b][d][t] ----------------
__global__ void tconv_kernel(const float* __restrict__ src, __nv_bfloat16* __restrict__ hi,
                             __nv_bfloat16* __restrict__ lo) {
    __shared__ float tile[32][33];
    int z = blockIdx.z, t0 = blockIdx.x * 32, d0 = blockIdx.y * 32;
    int tx = threadIdx.x, ty = threadIdx.y;
#pragma unroll
    for (int i = 0; i < 4; i++)
        tile[ty + i*8][tx] = src[((long)z*T_ + t0 + ty + i*8) * D_ + d0 + tx];
    __syncthreads();
#pragma unroll
    for (int i = 0; i < 4; i++) {
        float v = tile[tx][ty + i*8];
        long o = ((long)z*D_ + d0 + ty + i*8) * T_ + t0 + tx;
        __nv_bfloat16 h = __float2bfloat16(v);
        hi[o] = h; lo[o] = __float2bfloat16(v - __bfloat162float(h));
    }
}

__global__ void bsum_kernel(const float* a, const float* b, const float* a2, const float* b2) {
    int i = blockIdx.x * 256 + threadIdx.x;
    if (i < G_) { g_bsum_f[i] = a[i] + b[i]; g_bsum_b[i] = a2[i] + b2[i]; }
}

// ---------------- split-bf16 tensor-core GEMM (mma.sync, baseline PTX) ----------------
struct GemmP {
    const __nv_bfloat16 *Ah[2], *Al[2], *Bh[2], *Bl[2];
    int K[2], lda[2], ldb[2];
    long sA[2], sB[2];
    int nt;
    float* C; int ldc; long sC;
    const float* bias;
    __nv_bfloat16 *Chi, *Clo; int ldhl; long sHL;
};

#define SROW   40
#define TILEB  (128*SROW*2)
#define STAGEB (4*TILEB)
#define GEMM_SMEM (2*STAGEB)

__device__ __forceinline__ uint32_t smem_u32_of(const void* p) {
    uint32_t a;
    asm("{ .reg .u64 t; cvta.to.shared.u64 t, %1; cvt.u32.u64 %0, t; }" : "=r"(a) : "l"(p));
    return a;
}
__device__ __forceinline__ void cpasync16(uint32_t s, const void* g) {
    asm volatile("cp.async.cg.shared.global [%0], [%1], 16;" :: "r"(s), "l"(g));
}
__device__ __forceinline__ void cpcommit() { asm volatile("cp.async.commit_group;"); }
template<int N> __device__ __forceinline__ void cpwait() {
    asm volatile("cp.async.wait_group %0;" :: "n"(N));
}

#define MMA16816(d, a, b0v, b1v) \
    asm volatile("mma.sync.aligned.m16n8k16.row.col.f32.bf16.bf16.f32 " \
        "{%0,%1,%2,%3}, {%4,%5,%6,%7}, {%8,%9}, {%0,%1,%2,%3};" \
        : "+f"((d)[0]), "+f"((d)[1]), "+f"((d)[2]), "+f"((d)[3]) \
        : "r"((a)[0]), "r"((a)[1]), "r"((a)[2]), "r"((a)[3]), "r"(b0v), "r"(b1v))

__device__ __forceinline__ void issue_stage(
    const GemmP& P, int z, int c, int nc0, int buf,
    int tid, int bm, int bn, uint32_t sbase)
{
    int t  = (c < nc0) ? 0 : 1;
    int ch = (c < nc0) ? c : (c - nc0);
    const __nv_bfloat16* Ah = P.Ah[t] + (long)z * P.sA[t];
    const __nv_bfloat16* Al = P.Al[t] + (long)z * P.sA[t];
    const __nv_bfloat16* Bh = P.Bh[t] + (long)z * P.sB[t];
    const __nv_bfloat16* Bl = P.Bl[t] + (long)z * P.sB[t];
    int lda = P.lda[t], ldb = P.ldb[t];
    int kb0 = ch * 32;
#pragma unroll
    for (int i = 0; i < 8; i++) {
        int idx  = i * 256 + tid;
        int tile = idx >> 9;
        int cc   = idx & 511;
        int row  = cc >> 2;
        int seg  = cc & 3;
        uint32_t sa = sbase + buf * STAGEB + tile * TILEB + (row * SROW + seg * 8) * 2;
        int kb = kb0 + seg * 8;
        const __nv_bfloat16* src;
        if      (tile == 0) src = Ah + (long)(bm + row) * lda + kb;
        else if (tile == 1) src = Al + (long)(bm + row) * lda + kb;
        else if (tile == 2) src = Bh + (long)(bn + row) * ldb + kb;
        else                src = Bl + (long)(bn + row) * ldb + kb;
        cpasync16(sa, src);
    }
    cpcommit();
}

template<bool TANH, bool WF32, bool WBF16>
__global__ void __launch_bounds__(256, 2) mma_gemm_kernel(GemmP P) {
    extern __shared__ __align__(16) char smem[];
    const int tid = threadIdx.x, lane = tid & 31, wid = tid >> 5;
    const int g = lane >> 2, tg = lane & 3;
    const int wm = (wid & 3) * 32, wn = (wid >> 2) * 64;
    const int bn = blockIdx.x * 128, bm = blockIdx.y * 128, z = blockIdx.z;
    const uint32_t sbase = smem_u32_of(smem);

    float acc[2][8][4];
#pragma unroll
    for (int mt = 0; mt < 2; mt++)
#pragma unroll
        for (int nt = 0; nt < 8; nt++)
#pragma unroll
            for (int r = 0; r < 4; r++) acc[mt][nt][r] = 0.f;

    const int nc0 = P.K[0] >> 5;
    const int nct = nc0 + ((P.nt > 1) ? (P.K[1] >> 5) : 0);

    issue_stage(P, z, 0, nc0, 0, tid, bm, bn, sbase);

    for (int c = 0; c < nct; c++) {
        int buf = c & 1;
        if (c + 1 < nct) { issue_stage(P, z, c + 1, nc0, buf ^ 1, tid, bm, bn, sbase); cpwait<1>(); }
        else             { cpwait<0>(); }
        __syncthreads();

        const __nv_bfloat16* Ash = (const __nv_bfloat16*)(smem + buf * STAGEB);
        const __nv_bfloat16* Asl = Ash + 128 * SROW;
        const __nv_bfloat16* Bsh = Asl + 128 * SROW;
        const __nv_bfloat16* Bsl = Bsh + 128 * SROW;

#pragma unroll
        for (int s = 0; s < 2; s++) {
            int k0 = s * 16;
            uint32_t ah[2][4], al[2][4];
#pragma unroll
            for (int mt = 0; mt < 2; mt++) {
                int r = wm + mt * 16 + g;
                ah[mt][0] = *(const uint32_t*)&Ash[(r    ) * SROW + k0     + tg * 2];
                ah[mt][1] = *(const uint32_t*)&Ash[(r + 8) * SROW + k0     + tg * 2];
                ah[mt][2] = *(const uint32_t*)&Ash[(r    ) * SROW + k0 + 8 + tg * 2];
                ah[mt][3] = *(const uint32_t*)&Ash[(r + 8) * SROW + k0 + 8 + tg * 2];
                al[mt][0] = *(const uint32_t*)&Asl[(r    ) * SROW + k0     + tg * 2];
                al[mt][1] = *(const uint32_t*)&Asl[(r + 8) * SROW + k0     + tg * 2];
                al[mt][2] = *(const uint32_t*)&Asl[(r    ) * SROW + k0 + 8 + tg * 2];
                al[mt][3] = *(const uint32_t*)&Asl[(r + 8) * SROW + k0 + 8 + tg * 2];
            }
#pragma unroll
            for (int nt = 0; nt < 8; nt++) {
                int n = wn + nt * 8 + g;
                uint32_t bh0 = *(const uint32_t*)&Bsh[n * SROW + k0     + tg * 2];
                uint32_t bh1 = *(const uint32_t*)&Bsh[n * SROW + k0 + 8 + tg * 2];
                uint32_t bl0 = *(const uint32_t*)&Bsl[n * SROW + k0     + tg * 2];
                uint32_t bl1 = *(const uint32_t*)&Bsl[n * SROW + k0 + 8 + tg * 2];
#pragma unroll
                for (int mt = 0; mt < 2; mt++) {
                    MMA16816(acc[mt][nt], ah[mt], bh0, bh1);
                    MMA16816(acc[mt][nt], ah[mt], bl0, bl1);
                    MMA16816(acc[mt][nt], al[mt], bh0, bh1);
                }
            }
        }
        __syncthreads();
    }

#pragma unroll
    for (int mt = 0; mt < 2; mt++) {
#pragma unroll
        for (int nt = 0; nt < 8; nt++) {
            int col = bn + wn + nt * 8 + tg * 2;
            float bv0 = P.bias ? P.bias[col]     : 0.f;
            float bv1 = P.bias ? P.bias[col + 1] : 0.f;
#pragma unroll
            for (int h = 0; h < 2; h++) {
                int row = bm + wm + mt * 16 + g + h * 8;
                float v0 = acc[mt][nt][h * 2]     + bv0;
                float v1 = acc[mt][nt][h * 2 + 1] + bv1;
                if (TANH) { v0 = tanhf(v0); v1 = tanhf(v1); }
                if (WF32) {
                    float* cp = P.C + (long)z * P.sC + (long)row * P.ldc + col;
                    cp[0] = v0; cp[1] = v1;
                }
                if (WBF16) {
                    long o = (long)z * P.sHL + (long)row * P.ldhl + col;
                    __nv_bfloat16 h0 = __float2bfloat16(v0);
                    __nv_bfloat16 h1 = __float2bfloat16(v1);
                    P.Chi[o] = h0; P.Chi[o + 1] = h1;
                    P.Clo[o]     = __float2bfloat16(v0 - __bfloat162float(h0));
                    P.Clo[o + 1] = __float2bfloat16(v1 - __bfloat162float(h1));
                }
            }
        }
    }
}

// ---------------- persistent bidirectional LSTM (tensor-core, full-K, flag barrier) ----------------
// Distributed barrier: each block release-stores its counter into its own padded slot;
// 128 threads each poll one flag. No same-address atomic serialization.
__device__ __forceinline__ void gbar(unsigned bc) {
    __threadfence();
    __syncthreads();
    if (threadIdx.x == 0) g_flags[blockIdx.x * 8] = bc;
    if (threadIdx.x < NB_LSTM) {
        while (g_flags[threadIdx.x * 8] < bc) { __nanosleep(20); }
    }
    __threadfence();
    __syncthreads();
}
__global__ void reset_kernel() {
    if (threadIdx.x < NB_LSTM) g_flags[threadIdx.x * 8] = 0u;
}

// smem layout (bytes)
#define LS_WS_H 0
#define LS_WS_L 33280
#define LS_HS_H 66560
#define LS_HS_L 133120
#define LS_SG   199680
#define LSTM_SMEM (199680 + 64*33*4)

// 128 blocks = 2 dirs x 64. Block owns 8 hidden units (32 gate-cols) over full K=512.
__global__ void __launch_bounds__(256, 1) lstm_kernel(
    const float* __restrict__ whf, const float* __restrict__ whb)
{
    extern __shared__ __align__(16) char smem[];
    __nv_bfloat16* WS_h = (__nv_bfloat16*)(smem + LS_WS_H);
    __nv_bfloat16* WS_l = (__nv_bfloat16*)(smem + LS_WS_L);
    __nv_bfloat16* HS_h = (__nv_bfloat16*)(smem + LS_HS_H);
    __nv_bfloat16* HS_l = (__nv_bfloat16*)(smem + LS_HS_L);
    float* SG = (float*)(smem + LS_SG);          // [64][33] gate sums
    const uint32_t sbase = smem_u32_of(smem);

    const int tid = threadIdx.x, lane = tid & 31, wid = tid >> 5;
    const int g = lane >> 2, tg = lane & 3;
    const int bid = blockIdx.x;
    const int dir = bid >> 6, b64 = bid & 63;
    const float* W    = dir ? whb : whf;           // [2048][512]
    const float* xpre = dir ? g_xpre_b : g_xpre_f;

    // preload W slice: rows r = gate*8 + j  (gate-col = gate*512 + b64*8 + j), split bf16
    for (int idx = tid; idx < 32 * 512; idx += 256) {
        int r = idx >> 9, k = idx & 511;
        int gg = r >> 3, j = r & 7;
        float v = W[(long)(gg * H_ + b64 * 8 + j) * H_ + k];
        __nv_bfloat16 h = __float2bfloat16(v);
        WS_h[r * 520 + k] = h;
        WS_l[r * 520 + k] = __float2bfloat16(v - __bfloat162float(h));
    }
    __syncthreads();

    const int m0 = (wid & 3) * 16, n0 = (wid >> 2) * 16;   // 8 warps: 4m x 2n, warp tile 16x16
    const int v0 = tid * 2;
    const int ub0 = v0 >> 3, uj0 = v0 & 7;
    const int col0 = b64 * 8 + uj0;
    float creg0 = 0.f, creg1 = 0.f;
    unsigned bc = 0;

    for (int s = 0; s < T_; s++) {
        int t = dir ? (T_ - 1 - s) : s;
        int wbuf = s & 1, rbuf = wbuf ^ 1;

        // prefetch xpre gates for this thread's 2 cells (independent of h)
        float xg0[4], xg1[4];
        {
            const float* xp = xpre + ((long)ub0 * T_ + t) * G_ + b64 * 8 + uj0;
#pragma unroll
            for (int q = 0; q < 4; q++) { xg0[q] = __ldcg(&xp[q * H_]); xg1[q] = __ldcg(&xp[q * H_ + 1]); }
        }

        if (s > 0) {
            // stage h (prev step) from global split-bf16 into smem
            const __nv_bfloat16* Hh = g_hhi[dir][rbuf];
            const __nv_bfloat16* Hl = g_hlo[dir][rbuf];
            for (int c = tid; c < 8192; c += 256) {
                int arr = c >> 12;
                int cc  = c & 4095;
                int row = cc >> 6, seg = cc & 63;
                uint32_t sa = sbase + (arr ? LS_HS_L : LS_HS_H) + row * 1040 + seg * 16;
                const __nv_bfloat16* src = (arr ? Hl : Hh) + row * H_ + seg * 8;
                cpasync16(sa, src);
            }
            cpcommit(); cpwait<0>();
            __syncthreads();

            float acc[2][4];
#pragma unroll
            for (int nt = 0; nt < 2; nt++)
#pragma unroll
                for (int r = 0; r < 4; r++) acc[nt][r] = 0.f;

#pragma unroll 4
            for (int ks = 0; ks < 32; ks++) {
                int kw = ks * 16;
                uint32_t ah[4], al[4];
                ah[0] = *(const uint32_t*)&HS_h[(m0 + g    ) * 520 + kw     + tg * 2];
                ah[1] = *(const uint32_t*)&HS_h[(m0 + g + 8) * 520 + kw     + tg * 2];
                ah[2] = *(const uint32_t*)&HS_h[(m0 + g    ) * 520 + kw + 8 + tg * 2];
                ah[3] = *(const uint32_t*)&HS_h[(m0 + g + 8) * 520 + kw + 8 + tg * 2];
                al[0] = *(const uint32_t*)&HS_l[(m0 + g    ) * 520 + kw     + tg * 2];
                al[1] = *(const uint32_t*)&HS_l[(m0 + g + 8) * 520 + kw     + tg * 2];
                al[2] = *(const uint32_t*)&HS_l[(m0 + g    ) * 520 + kw + 8 + tg * 2];
                al[3] = *(const uint32_t*)&HS_l[(m0 + g + 8) * 520 + kw + 8 + tg * 2];
#pragma unroll
                for (int nt = 0; nt < 2; nt++) {
                    int n = n0 + nt * 8 + g;
                    uint32_t bh0 = *(const uint32_t*)&WS_h[n * 520 + kw     + tg * 2];
                    uint32_t bh1 = *(const uint32_t*)&WS_h[n * 520 + kw + 8 + tg * 2];
                    uint32_t bl0 = *(const uint32_t*)&WS_l[n * 520 + kw     + tg * 2];
                    uint32_t bl1 = *(const uint32_t*)&WS_l[n * 520 + kw + 8 + tg * 2];
                    MMA16816(acc[nt], ah, bh0, bh1);
                    MMA16816(acc[nt], ah, bl0, bl1);
                    MMA16816(acc[nt], al, bh0, bh1);
                }
            }
            // route accumulators to SG[batch][gatecol 0..31]
#pragma unroll
            for (int nt = 0; nt < 2; nt++) {
                int col = n0 + nt * 8 + tg * 2;
                SG[(m0 + g    ) * 33 + col    ] = acc[nt][0];
                SG[(m0 + g    ) * 33 + col + 1] = acc[nt][1];
                SG[(m0 + g + 8) * 33 + col    ] = acc[nt][2];
                SG[(m0 + g + 8) * 33 + col + 1] = acc[nt][3];
            }
            __syncthreads();
        }

        // cell update (2 values per thread)
        {
            float gv0[4], gv1[4];
#pragma unroll
            for (int q = 0; q < 4; q++) {
                float a0 = xg0[q], a1 = xg1[q];
                if (s > 0) {
                    a0 += SG[ub0 * 33 + q * 8 + uj0];
                    a1 += SG[ub0 * 33 + q * 8 + uj0 + 1];
                }
                gv0[q] = a0; gv1[q] = a1;
            }
            float i0 = 1.f / (1.f + expf(-gv0[0]));
            float f0 = 1.f / (1.f + expf(-gv0[1]));
            float c0 = tanhf(gv0[2]);
            float o0 = 1.f / (1.f + expf(-gv0[3]));
            creg0 = f0 * creg0 + i0 * c0;
            float h0 = o0 * tanhf(creg0);

            float i1 = 1.f / (1.f + expf(-gv1[0]));
            float f1 = 1.f / (1.f + expf(-gv1[1]));
            float c1 = tanhf(gv1[2]);
            float o1 = 1.f / (1.f + expf(-gv1[3]));
            creg1 = f1 * creg1 + i1 * c1;
            float h1 = o1 * tanhf(creg1);

            long co = ((long)ub0 * T_ + t) * D_ + dir * H_ + col0;
            __nv_bfloat16 hh0 = __float2bfloat16(h0);
            __nv_bfloat16 hh1 = __float2bfloat16(h1);
            __nv_bfloat16 hl0 = __float2bfloat16(h0 - __bfloat162float(hh0));
            __nv_bfloat16 hl1 = __float2bfloat16(h1 - __bfloat162float(hh1));
            g_ctx[co]     = h0;
            g_ctx[co + 1] = h1;
            g_ch[co] = hh0; g_ch[co + 1] = hh1;     // ctx split emitted in-scan
            g_cl[co] = hl0; g_cl[co + 1] = hl1;
            __nv_bfloat16* Hh = g_hhi[dir][wbuf];
            __nv_bfloat16* Hl = g_hlo[dir][wbuf];
            Hh[ub0 * H_ + col0]     = hh0;
            Hh[ub0 * H_ + col0 + 1] = hh1;
            Hl[ub0 * H_ + col0]     = hl0;
            Hl[ub0 * H_ + col0 + 1] = hl1;
        }
        gbar(++bc);
    }
}

// ---------------- softmax / mean / head / bn ----------------
__global__ void softmax_kernel(const unsigned char* __restrict__ mask) {
    int row = blockIdx.x;
    int tid = threadIdx.x;
    int b = row >> 8;
    float v = g_scores[(long)row * T_ + tid];
    if (mask[b * T_ + tid]) v = -INFINITY;
    __shared__ float red[256];
    red[tid] = v; __syncthreads();
    for (int s = 128; s > 0; s >>= 1) {
        if (tid < s) red[tid] = fmaxf(red[tid], red[tid + s]);
        __syncthreads();
    }
    float m = red[0]; __syncthreads();
    float e = __expf(v - m);
    red[tid] = e; __syncthreads();
    for (int s = 128; s > 0; s >>= 1) {
        if (tid < s) red[tid] += red[tid + s];
        __syncthreads();
    }
    g_scores[(long)row * T_ + tid] = e / red[0];
}

__global__ void mean_kernel() {
    int idx = blockIdx.x * 256 + threadIdx.x;
    int b = idx >> 10, d = idx & 1023;
    const float* p = &g_htilde[(long)b * T_ * D_ + d];
    float s = 0.f;
    for (int t = 0; t < T_; t++) s += p[(long)t * D_];
    g_ctxout[idx] = s * (1.0f / T_);
}

__global__ void yhead_kernel(const float* __restrict__ w_out, const float* __restrict__ b_out) {
    int m = blockIdx.x, tid = threadIdx.x;
    int wid = tid >> 5, lid = tid & 31;
    const float* x = &g_ctxout[m * D_];
    for (int n = wid; n < OUT_; n += 8) {
        const float* w = &w_out[(long)n * D_];
        float s = 0.f;
        for (int k = lid; k < D_; k += 32) s += x[k] * w[k];
#pragma unroll
        for (int o = 16; o > 0; o >>= 1) s += __shfl_down_sync(0xffffffffu, s, o);
        if (lid == 0) g_y[m * OUT_ + n] = tanhf(s + b_out[n]);
    }
}

__global__ void bn_kernel(const float* __restrict__ gamma, const float* __restrict__ beta,
                          float* __restrict__ out) {
    int n = threadIdx.x;
    float mu = 0.f;
    for (int b = 0; b < B_; b++) mu += g_y[b * OUT_ + n];
    mu *= (1.0f / B_);
    float var = 0.f;
    for (int b = 0; b < B_; b++) { float d = g_y[b * OUT_ + n] - mu; var += d * d; }
    var *= (1.0f / B_);
    float inv = rsqrtf(var + 1e-5f);
    float ga = gamma[n], be = beta[n];
    for (int b = 0; b < B_; b++)
        out[b * OUT_ + n] = ga * (g_y[b * OUT_ + n] - mu) * inv + be;
}

// ---------------- host launcher ----------------
static inline void conv(const float* s, __nv_bfloat16* h, __nv_bfloat16* l,
                        int rows, int scols, int sld, int dld) {
    long tot = (long)rows * dld;
    conv_kernel<<<(unsigned)((tot + 255) / 256), 256>>>(s, h, l, rows, scols, sld, dld);
}

extern "C" void kernel_launch(void* const* d_in, const int* in_sizes, int n_in,
                              void* d_out, int out_size) {
    const int*   inputs = (const int*)d_in[0];
    const unsigned char* mask = (const unsigned char*)d_in[1];
    const float* table  = (const float*)d_in[2];
    const float* w_ih_f = (const float*)d_in[3];
    const float* w_hh_f = (const float*)d_in[4];
    const float* b_ih_f = (const float*)d_in[5];
    const float* b_hh_f = (const float*)d_in[6];
    const float* w_ih_b = (const float*)d_in[7];
    const float* w_hh_b = (const float*)d_in[8];
    const float* b_ih_b = (const float*)d_in[9];
    const float* b_hh_b = (const float*)d_in[10];
    const float* w_in   = (const float*)d_in[11];
    const float* w_attn = (const float*)d_in[12];
    const float* w_out  = (const float*)d_in[13];
    const float* b_out  = (const float*)d_in[14];
    const float* gamma  = (const float*)d_in[15];
    const float* beta   = (const float*)d_in[16];
    float* out = (float*)d_out;

    float *embeds, *xf, *xb, *ctx, *scores, *htilde, *bsf, *bsb;
    cudaGetSymbolAddress((void**)&embeds, g_embeds);
    cudaGetSymbolAddress((void**)&xf,     g_xpre_f);
    cudaGetSymbolAddress((void**)&xb,     g_xpre_b);
    cudaGetSymbolAddress((void**)&ctx,    g_ctx);
    cudaGetSymbolAddress((void**)&scores, g_scores);
    cudaGetSymbolAddress((void**)&htilde, g_htilde);
    cudaGetSymbolAddress((void**)&bsf,    g_bsum_f);
    cudaGetSymbolAddress((void**)&bsb,    g_bsum_b);
    __nv_bfloat16 *eh,*el,*wfh,*wfl,*wbh,*wbl,*ch,*cl,*cth,*ctl,*winh,*winl,
                  *th,*tl,*ah,*al,*w1h,*w1l,*w2h,*w2l,*wh,*wl;
    cudaGetSymbolAddress((void**)&eh, g_eh);   cudaGetSymbolAddress((void**)&el, g_el);
    cudaGetSymbolAddress((void**)&wfh, g_wfh); cudaGetSymbolAddress((void**)&wfl, g_wfl);
    cudaGetSymbolAddress((void**)&wbh, g_wbh); cudaGetSymbolAddress((void**)&wbl, g_wbl);
    cudaGetSymbolAddress((void**)&ch, g_ch);   cudaGetSymbolAddress((void**)&cl, g_cl);
    cudaGetSymbolAddress((void**)&cth, g_cth); cudaGetSymbolAddress((void**)&ctl, g_ctl);
    cudaGetSymbolAddress((void**)&winh, g_winh); cudaGetSymbolAddress((void**)&winl, g_winl);
    cudaGetSymbolAddress((void**)&th, g_th);   cudaGetSymbolAddress((void**)&tl, g_tl);
    cudaGetSymbolAddress((void**)&ah, g_ah);   cudaGetSymbolAddress((void**)&al, g_al);
    cudaGetSymbolAddress((void**)&w1h, g_w1h); cudaGetSymbolAddress((void**)&w1l, g_w1l);
    cudaGetSymbolAddress((void**)&w2h, g_w2h); cudaGetSymbolAddress((void**)&w2l, g_w2l);
    cudaGetSymbolAddress((void**)&wh, g_wh);   cudaGetSymbolAddress((void**)&wl, g_wl);

    cudaFuncSetAttribute(mma_gemm_kernel<false,true,false>,
                         cudaFuncAttributeMaxDynamicSharedMemorySize, GEMM_SMEM);
    cudaFuncSetAttribute(mma_gemm_kernel<false,false,true>,
                         cudaFuncAttributeMaxDynamicSharedMemorySize, GEMM_SMEM);
    cudaFuncSetAttribute(mma_gemm_kernel<true,true,false>,
                         cudaFuncAttributeMaxDynamicSharedMemorySize, GEMM_SMEM);

    // 1. embed + operand conversions
    embed_kernel<<<(BT_*E_ + 255) / 256, 256>>>(inputs, table);
    conv(embeds, eh, el, BT_, E_, E_, EP_);
    conv(w_ih_f, wfh, wfl, G_, E_, E_, EP_);
    conv(w_ih_b, wbh, wbl, G_, E_, E_, EP_);
    conv(w_in,   winh, winl, D_, D_, D_, D_);
    conv(w_attn,        w1h, w1l, D_, D_, 2*D_, D_);
    conv(w_attn + D_,   w2h, w2l, D_, D_, 2*D_, D_);
    bsum_kernel<<<(G_ + 255) / 256, 256>>>(b_ih_f, b_hh_f, b_ih_b, b_hh_b);

    // 2. xpre = embeds @ w_ih^T + (b_ih + b_hh)
    {
        GemmP P{};
        P.nt = 1; P.K[0] = EP_; P.lda[0] = EP_; P.ldb[0] = EP_;
        P.Ah[0] = eh; P.Al[0] = el; P.ldc = G_;
        P.Bh[0] = wfh; P.Bl[0] = wfl; P.C = xf; P.bias = bsf;
        dim3 g(G_/128, BT_/128, 1);
        mma_gemm_kernel<false,true,false><<<g, 256, GEMM_SMEM>>>(P);
        P.Bh[0] = wbh; P.Bl[0] = wbl; P.C = xb; P.bias = bsb;
        mma_gemm_kernel<false,true,false><<<g, 256, GEMM_SMEM>>>(P);
    }

    // 3. persistent bidirectional LSTM (flag barrier; emits ctx fp32 + split bf16)
    reset_kernel<<<1, 128>>>();
    cudaFuncSetAttribute(lstm_kernel, cudaFuncAttributeMaxDynamicSharedMemorySize, LSTM_SMEM);
    lstm_kernel<<<NB_LSTM, 256, LSTM_SMEM>>>(w_hh_f, w_hh_b);

    // 4. ctx transposed split only (plain split now produced by the LSTM)
    tconv_kernel<<<dim3(T_/32, D_/32, B_), dim3(32, 8)>>>(ctx, cth, ctl);

    // 5. target = ctx @ w_in^T  (bf16 hi/lo out)
    {
        GemmP P{};
        P.nt = 1; P.K[0] = D_; P.lda[0] = D_; P.ldb[0] = D_;
        P.Ah[0] = ch; P.Al[0] = cl; P.Bh[0] = winh; P.Bl[0] = winl;
        P.Chi = th; P.Clo = tl; P.ldhl = D_;
        dim3 g(D_/128, BT_/128, 1);
        mma_gemm_kernel<false,false,true><<<g, 256, GEMM_SMEM>>>(P);
    }

    // 6. scores[z] = target[z] @ ctx[z]^T  (fp32 out)
    {
        GemmP P{};
        P.nt = 1; P.K[0] = D_; P.lda[0] = D_; P.ldb[0] = D_;
        P.Ah[0] = th; P.Al[0] = tl; P.sA[0] = (long)T_*D_;
        P.Bh[0] = ch; P.Bl[0] = cl; P.sB[0] = (long)T_*D_;
        P.C = scores; P.ldc = T_; P.sC = (long)T_*T_;
        dim3 g(T_/128, T_/128, B_);
        mma_gemm_kernel<false,true,false><<<g, 256, GEMM_SMEM>>>(P);
    }

    // 7. softmax + attn split
    softmax_kernel<<<BT_, 256>>>(mask);
    conv(scores, ah, al, BT_, T_, T_, T_);

    // 8. weighted[z] = attn[z] @ ctxT[z]^T  (bf16 hi/lo out)
    {
        GemmP P{};
        P.nt = 1; P.K[0] = T_; P.lda[0] = T_; P.ldb[0] = T_;
        P.Ah[0] = ah; P.Al[0] = al; P.sA[0] = (long)T_*T_;
        P.Bh[0] = cth; P.Bl[0] = ctl; P.sB[0] = (long)D_*T_;
        P.Chi = wh; P.Clo = wl; P.ldhl = D_; P.sHL = (long)T_*D_;
        dim3 g(D_/128, T_/128, B_);
        mma_gemm_kernel<false,false,true><<<g, 256, GEMM_SMEM>>>(P);
    }

    // 9. htilde = tanh(weighted @ W1^T + ctx @ W2^T)
    {
        GemmP P{};
        P.nt = 2;
        P.K[0] = D_; P.lda[0] = D_; P.ldb[0] = D_;
        P.Ah[0] = wh; P.Al[0] = wl; P.Bh[0] = w1h; P.Bl[0] = w1l;
        P.K[1] = D_; P.lda[1] = D_; P.ldb[1] = D_;
        P.Ah[1] = ch; P.Al[1] = cl; P.Bh[1] = w2h; P.Bl[1] = w2l;
        P.C = htilde; P.ldc = D_;
        dim3 g(D_/128, BT_/128, 1);
        mma_gemm_kernel<true,true,false><<<g, 256, GEMM_SMEM>>>(P);
    }

    // 10-12. mean, head, batchnorm
    mean_kernel<<<(B_*D_)/256, 256>>>();
    yhead_kernel<<<B_, 256>>>(w_out, b_out);
    bn_kernel<<<1, OUT_>>>(gamma, beta, out);
}

// round 14
// speedup vs baseline: 1.1405x; 1.1405x over previous
#include <cuda_runtime.h>
#include <cuda_bf16.h>
#include <cstdint>
#include <math.h>

#define B_   64
#define T_   256
#define E_   300
#define EP_  320
#define H_   512
#define D_   1024
#define G_   2048
#define OUT_ 256
#define NB_LSTM 128u
#define BT_  (B_*T_)

// ---------------- fp32 scratch ----------------
__device__ float g_embeds[BT_*E_];
__device__ float g_xpre_f[BT_*G_];
__device__ float g_xpre_b[BT_*G_];
__device__ float g_ctx[BT_*D_];
__device__ float g_scores[BT_*T_];
__device__ float g_htilde[BT_*D_];
__device__ float g_ctxout[B_*D_];
__device__ float g_y[B_*OUT_];
__device__ float g_bsum_f[G_];
__device__ float g_bsum_b[G_];
__device__ unsigned g_barA[16];    // two per-direction counters, 32B apart

// LSTM recurrent h, split bf16, double-buffered: [dir][buf][64*512]
__device__ __align__(16) __nv_bfloat16 g_hhi[2][2][B_*H_];
__device__ __align__(16) __nv_bfloat16 g_hlo[2][2][B_*H_];

// ---------------- bf16 hi/lo scratch (16B aligned) ----------------
__device__ __align__(16) __nv_bfloat16 g_eh[BT_*EP_],   g_el[BT_*EP_];
__device__ __align__(16) __nv_bfloat16 g_wfh[G_*EP_],   g_wfl[G_*EP_];
__device__ __align__(16) __nv_bfloat16 g_wbh[G_*EP_],   g_wbl[G_*EP_];
__device__ __align__(16) __nv_bfloat16 g_ch[BT_*D_],    g_cl[BT_*D_];
__device__ __align__(16) __nv_bfloat16 g_cth[B_*D_*T_], g_ctl[B_*D_*T_];
__device__ __align__(16) __nv_bfloat16 g_winh[D_*D_],   g_winl[D_*D_];
__device__ __align__(16) __nv_bfloat16 g_th[BT_*D_],    g_tl[BT_*D_];
__device__ __align__(16) __nv_bfloat16 g_ah[BT_*T_],    g_al[BT_*T_];
__device__ __align__(16) __nv_bfloat16 g_w1h[D_*D_],    g_w1l[D_*D_];
__device__ __align__(16) __nv_bfloat16 g_w2h[D_*D_],    g_w2l[D_*D_];
__device__ __align__(16) __nv_bfloat16 g_wh[BT_*D_],    g_wl[BT_*D_];

// ---------------- embedding ----------------
__global__ void embed_kernel(const int* __restrict__ inp, const float* __restrict__ table) {
    int idx = blockIdx.x * blockDim.x + threadIdx.x;
    if (idx >= BT_*E_) return;
    int bt = idx / E_, e = idx - bt * E_;
    g_embeds[idx] = table[(long)inp[bt] * E_ + e];
}

// ---------------- fp32 -> bf16 hi/lo split (with K pad) ----------------
__global__ void conv_kernel(const float* __restrict__ src, __nv_bfloat16* __restrict__ hi,
                            __nv_bfloat16* __restrict__ lo, int rows, int scols, int sld, int dld) {
    long idx = (long)blockIdx.x * 256 + threadIdx.x;
    if (idx >= (long)rows * dld) return;
    int r = idx / dld, c = idx - (long)r * dld;
    float v = (c < scols) ? src[(long)r * sld + c] : 0.f;
    __nv_bfloat16 h = __float2bfloat16(v);
    hi[idx] = h;
    lo[idx] = __float2bfloat16(v - __bfloat162float(h));
}

// ---------------- ctx transpose + split: [b][t][d] -> [b][d][t] ----------------
__global__ void tconv_kernel(const float* __restrict__ src, __nv_bfloat16* __restrict__ hi,
                             __nv_bfloat16* __restrict__ lo) {
    __shared__ float tile[32][33];
    int z = blockIdx.z, t0 = blockIdx.x * 32, d0 = blockIdx.y * 32;
    int tx = threadIdx.x, ty = threadIdx.y;
#pragma unroll
    for (int i = 0; i < 4; i++)
        tile[ty + i*8][tx] = src[((long)z*T_ + t0 + ty + i*8) * D_ + d0 + tx];
    __syncthreads();
#pragma unroll
    for (int i = 0; i < 4; i++) {
        float v = tile[tx][ty + i*8];
        long o = ((long)z*D_ + d0 + ty + i*8) * T_ + t0 + tx;
        __nv_bfloat16 h = __float2bfloat16(v);
        hi[o] = h; lo[o] = __float2bfloat16(v - __bfloat162float(h));
    }
}

__global__ void bsum_kernel(const float* a, const float* b, const float* a2, const float* b2) {
    int i = blockIdx.x * 256 + threadIdx.x;
    if (i < G_) { g_bsum_f[i] = a[i] + b[i]; g_bsum_b[i] = a2[i] + b2[i]; }
}

// ---------------- split-bf16 tensor-core GEMM (mma.sync, baseline PTX) ----------------
struct GemmP {
    const __nv_bfloat16 *Ah[2], *Al[2], *Bh[2], *Bl[2];
    int K[2], lda[2], ldb[2];
    long sA[2], sB[2];
    int nt;
    float* C; int ldc; long sC;
    const float* bias;
    __nv_bfloat16 *Chi, *Clo; int ldhl; long sHL;
};

#define SROW   40
#define TILEB  (128*SROW*2)
#define STAGEB (4*TILEB)
#define GEMM_SMEM (2*STAGEB)

__device__ __forceinline__ uint32_t smem_u32_of(const void* p) {
    uint32_t a;
    asm("{ .reg .u64 t; cvta.to.shared.u64 t, %1; cvt.u32.u64 %0, t; }" : "=r"(a) : "l"(p));
    return a;
}
__device__ __forceinline__ void cpasync16(uint32_t s, const void* g) {
    asm volatile("cp.async.cg.shared.global [%0], [%1], 16;" :: "r"(s), "l"(g));
}
__device__ __forceinline__ void cpcommit() { asm volatile("cp.async.commit_group;"); }
template<int N> __device__ __forceinline__ void cpwait() {
    asm volatile("cp.async.wait_group %0;" :: "n"(N));
}

#define MMA16816(d, a, b0v, b1v) \
    asm volatile("mma.sync.aligned.m16n8k16.row.col.f32.bf16.bf16.f32 " \
        "{%0,%1,%2,%3}, {%4,%5,%6,%7}, {%8,%9}, {%0,%1,%2,%3};" \
        : "+f"((d)[0]), "+f"((d)[1]), "+f"((d)[2]), "+f"((d)[3]) \
        : "r"((a)[0]), "r"((a)[1]), "r"((a)[2]), "r"((a)[3]), "r"(b0v), "r"(b1v))

__device__ __forceinline__ void issue_stage(
    const GemmP& P, int z, int c, int nc0, int buf,
    int tid, int bm, int bn, uint32_t sbase)
{
    int t  = (c < nc0) ? 0 : 1;
    int ch = (c < nc0) ? c : (c - nc0);
    const __nv_bfloat16* Ah = P.Ah[t] + (long)z * P.sA[t];
    const __nv_bfloat16* Al = P.Al[t] + (long)z * P.sA[t];
    const __nv_bfloat16* Bh = P.Bh[t] + (long)z * P.sB[t];
    const __nv_bfloat16* Bl = P.Bl[t] + (long)z * P.sB[t];
    int lda = P.lda[t], ldb = P.ldb[t];
    int kb0 = ch * 32;
#pragma unroll
    for (int i = 0; i < 8; i++) {
        int idx  = i * 256 + tid;
        int tile = idx >> 9;
        int cc   = idx & 511;
        int row  = cc >> 2;
        int seg  = cc & 3;
        uint32_t sa = sbase + buf * STAGEB + tile * TILEB + (row * SROW + seg * 8) * 2;
        int kb = kb0 + seg * 8;
        const __nv_bfloat16* src;
        if      (tile == 0) src = Ah + (long)(bm + row) * lda + kb;
        else if (tile == 1) src = Al + (long)(bm + row) * lda + kb;
        else if (tile == 2) src = Bh + (long)(bn + row) * ldb + kb;
        else                src = Bl + (long)(bn + row) * ldb + kb;
        cpasync16(sa, src);
    }
    cpcommit();
}

template<bool TANH, bool WF32, bool WBF16>
__global__ void __launch_bounds__(256, 2) mma_gemm_kernel(GemmP P) {
    extern __shared__ __align__(16) char smem[];
    const int tid = threadIdx.x, lane = tid & 31, wid = tid >> 5;
    const int g = lane >> 2, tg = lane & 3;
    const int wm = (wid & 3) * 32, wn = (wid >> 2) * 64;
    const int bn = blockIdx.x * 128, bm = blockIdx.y * 128, z = blockIdx.z;
    const uint32_t sbase = smem_u32_of(smem);

    float acc[2][8][4];
#pragma unroll
    for (int mt = 0; mt < 2; mt++)
#pragma unroll
        for (int nt = 0; nt < 8; nt++)
#pragma unroll
            for (int r = 0; r < 4; r++) acc[mt][nt][r] = 0.f;

    const int nc0 = P.K[0] >> 5;
    const int nct = nc0 + ((P.nt > 1) ? (P.K[1] >> 5) : 0);

    issue_stage(P, z, 0, nc0, 0, tid, bm, bn, sbase);

    for (int c = 0; c < nct; c++) {
        int buf = c & 1;
        if (c + 1 < nct) { issue_stage(P, z, c + 1, nc0, buf ^ 1, tid, bm, bn, sbase); cpwait<1>(); }
        else             { cpwait<0>(); }
        __syncthreads();

        const __nv_bfloat16* Ash = (const __nv_bfloat16*)(smem + buf * STAGEB);
        const __nv_bfloat16* Asl = Ash + 128 * SROW;
        const __nv_bfloat16* Bsh = Asl + 128 * SROW;
        const __nv_bfloat16* Bsl = Bsh + 128 * SROW;

#pragma unroll
        for (int s = 0; s < 2; s++) {
            int k0 = s * 16;
            uint32_t ah[2][4], al[2][4];
#pragma unroll
            for (int mt = 0; mt < 2; mt++) {
                int r = wm + mt * 16 + g;
                ah[mt][0] = *(const uint32_t*)&Ash[(r    ) * SROW + k0     + tg * 2];
                ah[mt][1] = *(const uint32_t*)&Ash[(r + 8) * SROW + k0     + tg * 2];
                ah[mt][2] = *(const uint32_t*)&Ash[(r    ) * SROW + k0 + 8 + tg * 2];
                ah[mt][3] = *(const uint32_t*)&Ash[(r + 8) * SROW + k0 + 8 + tg * 2];
                al[mt][0] = *(const uint32_t*)&Asl[(r    ) * SROW + k0     + tg * 2];
                al[mt][1] = *(const uint32_t*)&Asl[(r + 8) * SROW + k0     + tg * 2];
                al[mt][2] = *(const uint32_t*)&Asl[(r    ) * SROW + k0 + 8 + tg * 2];
                al[mt][3] = *(const uint32_t*)&Asl[(r + 8) * SROW + k0 + 8 + tg * 2];
            }
#pragma unroll
            for (int nt = 0; nt < 8; nt++) {
                int n = wn + nt * 8 + g;
                uint32_t bh0 = *(const uint32_t*)&Bsh[n * SROW + k0     + tg * 2];
                uint32_t bh1 = *(const uint32_t*)&Bsh[n * SROW + k0 + 8 + tg * 2];
                uint32_t bl0 = *(const uint32_t*)&Bsl[n * SROW + k0     + tg * 2];
                uint32_t bl1 = *(const uint32_t*)&Bsl[n * SROW + k0 + 8 + tg * 2];
#pragma unroll
                for (int mt = 0; mt < 2; mt++) {
                    MMA16816(acc[mt][nt], ah[mt], bh0, bh1);
                    MMA16816(acc[mt][nt], ah[mt], bl0, bl1);
                    MMA16816(acc[mt][nt], al[mt], bh0, bh1);
                }
            }
        }
        __syncthreads();
    }

#pragma unroll
    for (int mt = 0; mt < 2; mt++) {
#pragma unroll
        for (int nt = 0; nt < 8; nt++) {
            int col = bn + wn + nt * 8 + tg * 2;
            float bv0 = P.bias ? P.bias[col]     : 0.f;
            float bv1 = P.bias ? P.bias[col + 1] : 0.f;
#pragma unroll
            for (int h = 0; h < 2; h++) {
                int row = bm + wm + mt * 16 + g + h * 8;
                float v0 = acc[mt][nt][h * 2]     + bv0;
                float v1 = acc[mt][nt][h * 2 + 1] + bv1;
                if (TANH) { v0 = tanhf(v0); v1 = tanhf(v1); }
                if (WF32) {
                    float* cp = P.C + (long)z * P.sC + (long)row * P.ldc + col;
                    cp[0] = v0; cp[1] = v1;
                }
                if (WBF16) {
                    long o = (long)z * P.sHL + (long)row * P.ldhl + col;
                    __nv_bfloat16 h0 = __float2bfloat16(v0);
                    __nv_bfloat16 h1 = __float2bfloat16(v1);
                    P.Chi[o] = h0; P.Chi[o + 1] = h1;
                    P.Clo[o]     = __float2bfloat16(v0 - __bfloat162float(h0));
                    P.Clo[o + 1] = __float2bfloat16(v1 - __bfloat162float(h1));
                }
            }
        }
    }
}

// ---------------- persistent bidirectional LSTM (3-pass, per-direction split barrier) ----------------
__device__ __forceinline__ void gbar_arrive(int dir) {
    __threadfence();
    __syncthreads();
    if (threadIdx.x == 0) atomicAdd(&g_barA[dir * 8], 1u);
}
__device__ __forceinline__ void gbar_wait(int dir, unsigned bc) {
    if (threadIdx.x == 0) {
        unsigned target = bc * 64u;
        while (*((volatile unsigned*)&g_barA[dir * 8]) < target) { __nanosleep(32); }
        __threadfence();
    }
    __syncthreads();
}
__global__ void reset_kernel() { g_barA[0] = 0u; g_barA[8] = 0u; }

// smem layout (bytes): WS hi/lo [32][520], HS hi/lo [64][520], SG [64][33]
#define LS_WS_H 0
#define LS_WS_L 33280
#define LS_HS_H 66560
#define LS_HS_L 133120
#define LS_SG   199680
#define LSTM_SMEM (199680 + 64*33*4)

// 128 blocks = 2 dirs x 64. Block owns 8 hidden units (32 gate-cols) over full K=512.
__global__ void __launch_bounds__(256, 1) lstm_kernel(
    const float* __restrict__ whf, const float* __restrict__ whb)
{
    extern __shared__ __align__(16) char smem[];
    __nv_bfloat16* WS_h = (__nv_bfloat16*)(smem + LS_WS_H);
    __nv_bfloat16* WS_l = (__nv_bfloat16*)(smem + LS_WS_L);
    __nv_bfloat16* HS_h = (__nv_bfloat16*)(smem + LS_HS_H);
    __nv_bfloat16* HS_l = (__nv_bfloat16*)(smem + LS_HS_L);
    float* SG = (float*)(smem + LS_SG);          // [64][33] gate sums
    const uint32_t sbase = smem_u32_of(smem);

    const int tid = threadIdx.x, lane = tid & 31, wid = tid >> 5;
    const int g = lane >> 2, tg = lane & 3;
    const int bid = blockIdx.x;
    const int dir = bid >> 6, b64 = bid & 63;
    const float* W    = dir ? whb : whf;           // [2048][512]
    const float* xpre = dir ? g_xpre_b : g_xpre_f;

    // preload W slice: rows r = gate*8 + j  (gate-col = gate*512 + b64*8 + j), split bf16
    for (int idx = tid; idx < 32 * 512; idx += 256) {
        int r = idx >> 9, k = idx & 511;
        int gg = r >> 3, j = r & 7;
        float v = W[(long)(gg * H_ + b64 * 8 + j) * H_ + k];
        __nv_bfloat16 h = __float2bfloat16(v);
        WS_h[r * 520 + k] = h;
        WS_l[r * 520 + k] = __float2bfloat16(v - __bfloat162float(h));
    }
    __syncthreads();

    const int m0 = (wid & 3) * 16, n0 = (wid >> 2) * 16;   // 8 warps: 4m x 2n
    const int v0 = tid * 2;
    const int ub0 = v0 >> 3, uj0 = v0 & 7;
    const int col0 = b64 * 8 + uj0;
    float creg0 = 0.f, creg1 = 0.f;
    unsigned bc = 0;

    for (int s = 0; s < T_; s++) {
        int t = dir ? (T_ - 1 - s) : s;
        int wbuf = s & 1, rbuf = wbuf ^ 1;

        // prefetch xpre gates (independent of h) BEFORE the barrier wait
        float xg0[4], xg1[4];
        {
            const float* xp = xpre + ((long)ub0 * T_ + t) * G_ + b64 * 8 + uj0;
#pragma unroll
            for (int q = 0; q < 4; q++) { xg0[q] = __ldcg(&xp[q * H_]); xg1[q] = __ldcg(&xp[q * H_ + 1]); }
        }

        if (s > 0) {
            gbar_wait(dir, bc);   // all dir-peers finished step s-1 (h written + fenced)

            // stage h (prev step) from global split-bf16 into smem
            const __nv_bfloat16* Hh = g_hhi[dir][rbuf];
            const __nv_bfloat16* Hl = g_hlo[dir][rbuf];
            for (int c = tid; c < 8192; c += 256) {
                int arr = c >> 12;
                int cc  = c & 4095;
                int row = cc >> 6, seg = cc & 63;
                uint32_t sa = sbase + (arr ? LS_HS_L : LS_HS_H) + row * 1040 + seg * 16;
                const __nv_bfloat16* src = (arr ? Hl : Hh) + row * H_ + seg * 8;
                cpasync16(sa, src);
            }
            cpcommit(); cpwait<0>();
            __syncthreads();

            float acc[2][4];
#pragma unroll
            for (int nt = 0; nt < 2; nt++)
#pragma unroll
                for (int r = 0; r < 4; r++) acc[nt][r] = 0.f;

#pragma unroll 4
            for (int ks = 0; ks < 32; ks++) {
                int kw = ks * 16;
                uint32_t ah[4], al[4];
                ah[0] = *(const uint32_t*)&HS_h[(m0 + g    ) * 520 + kw     + tg * 2];
                ah[1] = *(const uint32_t*)&HS_h[(m0 + g + 8) * 520 + kw     + tg * 2];
                ah[2] = *(const uint32_t*)&HS_h[(m0 + g    ) * 520 + kw + 8 + tg * 2];
                ah[3] = *(const uint32_t*)&HS_h[(m0 + g + 8) * 520 + kw + 8 + tg * 2];
                al[0] = *(const uint32_t*)&HS_l[(m0 + g    ) * 520 + kw     + tg * 2];
                al[1] = *(const uint32_t*)&HS_l[(m0 + g + 8) * 520 + kw     + tg * 2];
                al[2] = *(const uint32_t*)&HS_l[(m0 + g    ) * 520 + kw + 8 + tg * 2];
                al[3] = *(const uint32_t*)&HS_l[(m0 + g + 8) * 520 + kw + 8 + tg * 2];
#pragma unroll
                for (int nt = 0; nt < 2; nt++) {
                    int n = n0 + nt * 8 + g;
                    uint32_t bh0 = *(const uint32_t*)&WS_h[n * 520 + kw     + tg * 2];
                    uint32_t bh1 = *(const uint32_t*)&WS_h[n * 520 + kw + 8 + tg * 2];
                    uint32_t bl0 = *(const uint32_t*)&WS_l[n * 520 + kw     + tg * 2];
                    uint32_t bl1 = *(const uint32_t*)&WS_l[n * 520 + kw + 8 + tg * 2];
                    MMA16816(acc[nt], ah, bh0, bh1);
                    MMA16816(acc[nt], ah, bl0, bl1);
                    MMA16816(acc[nt], al, bh0, bh1);
                }
            }
#pragma unroll
            for (int nt = 0; nt < 2; nt++) {
                int col = n0 + nt * 8 + tg * 2;
                SG[(m0 + g    ) * 33 + col    ] = acc[nt][0];
                SG[(m0 + g    ) * 33 + col + 1] = acc[nt][1];
                SG[(m0 + g + 8) * 33 + col    ] = acc[nt][2];
                SG[(m0 + g + 8) * 33 + col + 1] = acc[nt][3];
            }
            __syncthreads();
        }

        // cell update (2 values per thread)
        {
            float gv0[4], gv1[4];
#pragma unroll
            for (int q = 0; q < 4; q++) {
                float a0 = xg0[q], a1 = xg1[q];
                if (s > 0) {
                    a0 += SG[ub0 * 33 + q * 8 + uj0];
                    a1 += SG[ub0 * 33 + q * 8 + uj0 + 1];
                }
                gv0[q] = a0; gv1[q] = a1;
            }
            float i0 = 1.f / (1.f + expf(-gv0[0]));
            float f0 = 1.f / (1.f + expf(-gv0[1]));
            float c0 = tanhf(gv0[2]);
            float o0 = 1.f / (1.f + expf(-gv0[3]));
            creg0 = f0 * creg0 + i0 * c0;
            float h0 = o0 * tanhf(creg0);

            float i1 = 1.f / (1.f + expf(-gv1[0]));
            float f1 = 1.f / (1.f + expf(-gv1[1]));
            float c1 = tanhf(gv1[2]);
            float o1 = 1.f / (1.f + expf(-gv1[3]));
            creg1 = f1 * creg1 + i1 * c1;
            float h1 = o1 * tanhf(creg1);

            long co = ((long)ub0 * T_ + t) * D_ + dir * H_ + col0;
            __nv_bfloat16 hh0 = __float2bfloat16(h0);
            __nv_bfloat16 hh1 = __float2bfloat16(h1);
            __nv_bfloat16 hl0 = __float2bfloat16(h0 - __bfloat162float(hh0));
            __nv_bfloat16 hl1 = __float2bfloat16(h1 - __bfloat162float(hh1));
            g_ctx[co]     = h0;
            g_ctx[co + 1] = h1;
            g_ch[co] = hh0; g_ch[co + 1] = hh1;     // ctx split emitted in-scan
            g_cl[co] = hl0; g_cl[co + 1] = hl1;
            __nv_bfloat16* Hh = g_hhi[dir][wbuf];
            __nv_bfloat16* Hl = g_hlo[dir][wbuf];
            Hh[ub0 * H_ + col0]     = hh0;
            Hh[ub0 * H_ + col0 + 1] = hh1;
            Hl[ub0 * H_ + col0]     = hl0;
            Hl[ub0 * H_ + col0 + 1] = hl1;
        }
        gbar_arrive(dir); ++bc;
    }
}

// ---------------- softmax (fused attn hi/lo emit) / mean / head / bn ----------------
__global__ void softmax_kernel(const unsigned char* __restrict__ mask) {
    int row = blockIdx.x;
    int tid = threadIdx.x;
    int b = row >> 8;
    float v = g_scores[(long)row * T_ + tid];
    if (mask[b * T_ + tid]) v = -INFINITY;
    __shared__ float red[256];
    red[tid] = v; __syncthreads();
    for (int s = 128; s > 0; s >>= 1) {
        if (tid < s) red[tid] = fmaxf(red[tid], red[tid + s]);
        __syncthreads();
    }
    float m = red[0]; __syncthreads();
    float e = __expf(v - m);
    red[tid] = e; __syncthreads();
    for (int s = 128; s > 0; s >>= 1) {
        if (tid < s) red[tid] += red[tid + s];
        __syncthreads();
    }
    float a = e / red[0];
    long o = (long)row * T_ + tid;
    __nv_bfloat16 h = __float2bfloat16(a);
    g_ah[o] = h;
    g_al[o] = __float2bfloat16(a - __bfloat162float(h));
}

__global__ void mean_kernel() {
    int idx = blockIdx.x * 256 + threadIdx.x;
    int b = idx >> 10, d = idx & 1023;
    const float* p = &g_htilde[(long)b * T_ * D_ + d];
    float s = 0.f;
    for (int t = 0; t < T_; t++) s += p[(long)t * D_];
    g_ctxout[idx] = s * (1.0f / T_);
}

__global__ void yhead_kernel(const float* __restrict__ w_out, const float* __restrict__ b_out) {
    int m = blockIdx.x, tid = threadIdx.x;
    int wid = tid >> 5, lid = tid & 31;
    const float* x = &g_ctxout[m * D_];
    for (int n = wid; n < OUT_; n += 8) {
        const float* w = &w_out[(long)n * D_];
        float s = 0.f;
        for (int k = lid; k < D_; k += 32) s += x[k] * w[k];
#pragma unroll
        for (int o = 16; o > 0; o >>= 1) s += __shfl_down_sync(0xffffffffu, s, o);
        if (lid == 0) g_y[m * OUT_ + n] = tanhf(s + b_out[n]);
    }
}

__global__ void bn_kernel(const float* __restrict__ gamma, const float* __restrict__ beta,
                          float* __restrict__ out) {
    int n = threadIdx.x;
    float mu = 0.f;
    for (int b = 0; b < B_; b++) mu += g_y[b * OUT_ + n];
    mu *= (1.0f / B_);
    float var = 0.f;
    for (int b = 0; b < B_; b++) { float d = g_y[b * OUT_ + n] - mu; var += d * d; }
    var *= (1.0f / B_);
    float inv = rsqrtf(var + 1e-5f);
    float ga = gamma[n], be = beta[n];
    for (int b = 0; b < B_; b++)
        out[b * OUT_ + n] = ga * (g_y[b * OUT_ + n] - mu) * inv + be;
}

// ---------------- host launcher ----------------
static inline void conv(const float* s, __nv_bfloat16* h, __nv_bfloat16* l,
                        int rows, int scols, int sld, int dld) {
    long tot = (long)rows * dld;
    conv_kernel<<<(unsigned)((tot + 255) / 256), 256>>>(s, h, l, rows, scols, sld, dld);
}

extern "C" void kernel_launch(void* const* d_in, const int* in_sizes, int n_in,
                              void* d_out, int out_size) {
    const int*   inputs = (const int*)d_in[0];
    const unsigned char* mask = (const unsigned char*)d_in[1];
    const float* table  = (const float*)d_in[2];
    const float* w_ih_f = (const float*)d_in[3];
    const float* w_hh_f = (const float*)d_in[4];
    const float* b_ih_f = (const float*)d_in[5];
    const float* b_hh_f = (const float*)d_in[6];
    const float* w_ih_b = (const float*)d_in[7];
    const float* w_hh_b = (const float*)d_in[8];
    const float* b_ih_b = (const float*)d_in[9];
    const float* b_hh_b = (const float*)d_in[10];
    const float* w_in   = (const float*)d_in[11];
    const float* w_attn = (const float*)d_in[12];
    const float* w_out  = (const float*)d_in[13];
    const float* b_out  = (const float*)d_in[14];
    const float* gamma  = (const float*)d_in[15];
    const float* beta   = (const float*)d_in[16];
    float* out = (float*)d_out;

    float *embeds, *xf, *xb, *ctx, *scores, *htilde, *bsf, *bsb;
    cudaGetSymbolAddress((void**)&embeds, g_embeds);
    cudaGetSymbolAddress((void**)&xf,     g_xpre_f);
    cudaGetSymbolAddress((void**)&xb,     g_xpre_b);
    cudaGetSymbolAddress((void**)&ctx,    g_ctx);
    cudaGetSymbolAddress((void**)&scores, g_scores);
    cudaGetSymbolAddress((void**)&htilde, g_htilde);
    cudaGetSymbolAddress((void**)&bsf,    g_bsum_f);
    cudaGetSymbolAddress((void**)&bsb,    g_bsum_b);
    __nv_bfloat16 *eh,*el,*wfh,*wfl,*wbh,*wbl,*ch,*cl,*cth,*ctl,*winh,*winl,
                  *th,*tl,*ah,*al,*w1h,*w1l,*w2h,*w2l,*wh,*wl;
    cudaGetSymbolAddress((void**)&eh, g_eh);   cudaGetSymbolAddress((void**)&el, g_el);
    cudaGetSymbolAddress((void**)&wfh, g_wfh); cudaGetSymbolAddress((void**)&wfl, g_wfl);
    cudaGetSymbolAddress((void**)&wbh, g_wbh); cudaGetSymbolAddress((void**)&wbl, g_wbl);
    cudaGetSymbolAddress((void**)&ch, g_ch);   cudaGetSymbolAddress((void**)&cl, g_cl);
    cudaGetSymbolAddress((void**)&cth, g_cth); cudaGetSymbolAddress((void**)&ctl, g_ctl);
    cudaGetSymbolAddress((void**)&winh, g_winh); cudaGetSymbolAddress((void**)&winl, g_winl);
    cudaGetSymbolAddress((void**)&th, g_th);   cudaGetSymbolAddress((void**)&tl, g_tl);
    cudaGetSymbolAddress((void**)&ah, g_ah);   cudaGetSymbolAddress((void**)&al, g_al);
    cudaGetSymbolAddress((void**)&w1h, g_w1h); cudaGetSymbolAddress((void**)&w1l, g_w1l);
    cudaGetSymbolAddress((void**)&w2h, g_w2h); cudaGetSymbolAddress((void**)&w2l, g_w2l);
    cudaGetSymbolAddress((void**)&wh, g_wh);   cudaGetSymbolAddress((void**)&wl, g_wl);

    cudaFuncSetAttribute(mma_gemm_kernel<false,true,false>,
                         cudaFuncAttributeMaxDynamicSharedMemorySize, GEMM_SMEM);
    cudaFuncSetAttribute(mma_gemm_kernel<false,false,true>,
                         cudaFuncAttributeMaxDynamicSharedMemorySize, GEMM_SMEM);
    cudaFuncSetAttribute(mma_gemm_kernel<true,true,false>,
                         cudaFuncAttributeMaxDynamicSharedMemorySize, GEMM_SMEM);

    // 1. embed + operand conversions
    embed_kernel<<<(BT_*E_ + 255) / 256, 256>>>(inputs, table);
    conv(embeds, eh, el, BT_, E_, E_, EP_);
    conv(w_ih_f, wfh, wfl, G_, E_, E_, EP_);
    conv(w_ih_b, wbh, wbl, G_, E_, E_, EP_);
    conv(w_in,   winh, winl, D_, D_, D_, D_);
    conv(w_attn,        w1h, w1l, D_, D_, 2*D_, D_);
    conv(w_attn + D_,   w2h, w2l, D_, D_, 2*D_, D_);
    bsum_kernel<<<(G_ + 255) / 256, 256>>>(b_ih_f, b_hh_f, b_ih_b, b_hh_b);

    // 2. xpre = embeds @ w_ih^T + (b_ih + b_hh)
    {
        GemmP P{};
        P.nt = 1; P.K[0] = EP_; P.lda[0] = EP_; P.ldb[0] = EP_;
        P.Ah[0] = eh; P.Al[0] = el; P.ldc = G_;
        P.Bh[0] = wfh; P.Bl[0] = wfl; P.C = xf; P.bias = bsf;
        dim3 g(G_/128, BT_/128, 1);
        mma_gemm_kernel<false,true,false><<<g, 256, GEMM_SMEM>>>(P);
        P.Bh[0] = wbh; P.Bl[0] = wbl; P.C = xb; P.bias = bsb;
        mma_gemm_kernel<false,true,false><<<g, 256, GEMM_SMEM>>>(P);
    }

    // 3. persistent bidirectional LSTM (split per-dir barrier; emits ctx fp32 + split)
    reset_kernel<<<1, 1>>>();
    cudaFuncSetAttribute(lstm_kernel, cudaFuncAttributeMaxDynamicSharedMemorySize, LSTM_SMEM);
    lstm_kernel<<<NB_LSTM, 256, LSTM_SMEM>>>(w_hh_f, w_hh_b);

    // 4. ctx transposed split only (plain split produced by the LSTM)
    tconv_kernel<<<dim3(T_/32, D_/32, B_), dim3(32, 8)>>>(ctx, cth, ctl);

    // 5. target = ctx @ w_in^T  (bf16 hi/lo out)
    {
        GemmP P{};
        P.nt = 1; P.K[0] = D_; P.lda[0] = D_; P.ldb[0] = D_;
        P.Ah[0] = ch; P.Al[0] = cl; P.Bh[0] = winh; P.Bl[0] = winl;
        P.Chi = th; P.Clo = tl; P.ldhl = D_;
        dim3 g(D_/128, BT_/128, 1);
        mma_gemm_kernel<false,false,true><<<g, 256, GEMM_SMEM>>>(P);
    }

    // 6. scores[z] = target[z] @ ctx[z]^T  (fp32 out)
    {
        GemmP P{};
        P.nt = 1; P.K[0] = D_; P.lda[0] = D_; P.ldb[0] = D_;
        P.Ah[0] = th; P.Al[0] = tl; P.sA[0] = (long)T_*D_;
        P.Bh[0] = ch; P.Bl[0] = cl; P.sB[0] = (long)T_*D_;
        P.C = scores; P.ldc = T_; P.sC = (long)T_*T_;
        dim3 g(T_/128, T_/128, B_);
        mma_gemm_kernel<false,true,false><<<g, 256, GEMM_SMEM>>>(P);
    }

    // 7. softmax (emits attn bf16 hi/lo directly)
    softmax_kernel<<<BT_, 256>>>(mask);

    // 8. weighted[z] = attn[z] @ ctxT[z]^T  (bf16 hi/lo out)
    {
        GemmP P{};
        P.nt = 1; P.K[0] = T_; P.lda[0] = T_; P.ldb[0] = T_;
        P.Ah[0] = ah; P.Al[0] = al; P.sA[0] = (long)T_*T_;
        P.Bh[0] = cth; P.Bl[0] = ctl; P.sB[0] = (long)D_*T_;
        P.Chi = wh; P.Clo = wl; P.ldhl = D_; P.sHL = (long)T_*D_;
        dim3 g(D_/128, T_/128, B_);
        mma_gemm_kernel<false,false,true><<<g, 256, GEMM_SMEM>>>(P);
    }

    // 9. htilde = tanh(weighted @ W1^T + ctx @ W2^T)
    {
        GemmP P{};
        P.nt = 2;
        P.K[0] = D_; P.lda[0] = D_; P.ldb[0] = D_;
        P.Ah[0] = wh; P.Al[0] = wl; P.Bh[0] = w1h; P.Bl[0] = w1l;
        P.K[1] = D_; P.lda[1] = D_; P.ldb[1] = D_;
        P.Ah[1] = ch; P.Al[1] = cl; P.Bh[1] = w2h; P.Bl[1] = w2l;
        P.C = htilde; P.ldc = D_;
        dim3 g(D_/128, BT_/128, 1);
        mma_gemm_kernel<true,true,false><<<g, 256, GEMM_SMEM>>>(P);
    }

    // 10-12. mean, head, batchnorm
    mean_kernel<<<(B_*D_)/256, 256>>>();
    yhead_kernel<<<B_, 256>>>(w_out, b_out);
    bn_kernel<<<1, OUT_>>>(gamma, beta, out);
}

// round 15
// speedup vs baseline: 1.1746x; 1.0299x over previous
#include <cuda_runtime.h>
#include <cuda_bf16.h>
#include <cstdint>
#include <math.h>

#define B_   64
#define T_   256
#define E_   300
#define EP_  320
#define H_   512
#define D_   1024
#define G_   2048
#define OUT_ 256
#define NB_LSTM 128u
#define BT_  (B_*T_)

// ---------------- fp32 scratch ----------------
__device__ float g_embeds[BT_*E_];
__device__ float g_xpre_f[BT_*G_];
__device__ float g_xpre_b[BT_*G_];
__device__ float g_ctx[BT_*D_];
__device__ float g_scores[BT_*T_];
__device__ float g_htilde[BT_*D_];
__device__ float g_ctxout[B_*D_];
__device__ float g_y[B_*OUT_];
__device__ float g_bsum_f[G_];
__device__ float g_bsum_b[G_];
__device__ unsigned g_barA[16];    // two per-direction counters, 32B apart

// LSTM recurrent h, split bf16, double-buffered: [dir][buf][64*512]
__device__ __align__(16) __nv_bfloat16 g_hhi[2][2][B_*H_];
__device__ __align__(16) __nv_bfloat16 g_hlo[2][2][B_*H_];

// ---------------- bf16 hi/lo scratch (16B aligned) ----------------
__device__ __align__(16) __nv_bfloat16 g_eh[BT_*EP_],   g_el[BT_*EP_];
__device__ __align__(16) __nv_bfloat16 g_wfh[G_*EP_],   g_wfl[G_*EP_];
__device__ __align__(16) __nv_bfloat16 g_wbh[G_*EP_],   g_wbl[G_*EP_];
__device__ __align__(16) __nv_bfloat16 g_ch[BT_*D_],    g_cl[BT_*D_];
__device__ __align__(16) __nv_bfloat16 g_cth[B_*D_*T_], g_ctl[B_*D_*T_];
__device__ __align__(16) __nv_bfloat16 g_winh[D_*D_],   g_winl[D_*D_];
__device__ __align__(16) __nv_bfloat16 g_th[BT_*D_],    g_tl[BT_*D_];
__device__ __align__(16) __nv_bfloat16 g_ah[BT_*T_],    g_al[BT_*T_];
__device__ __align__(16) __nv_bfloat16 g_w1h[D_*D_],    g_w1l[D_*D_];
__device__ __align__(16) __nv_bfloat16 g_w2h[D_*D_],    g_w2l[D_*D_];
__device__ __align__(16) __nv_bfloat16 g_wh[BT_*D_],    g_wl[BT_*D_];

// ---------------- embedding ----------------
__global__ void embed_kernel(const int* __restrict__ inp, const float* __restrict__ table) {
    int idx = blockIdx.x * blockDim.x + threadIdx.x;
    if (idx >= BT_*E_) return;
    int bt = idx / E_, e = idx - bt * E_;
    g_embeds[idx] = table[(long)inp[bt] * E_ + e];
}

// ---------------- fp32 -> bf16 hi/lo split (with K pad) ----------------
__global__ void conv_kernel(const float* __restrict__ src, __nv_bfloat16* __restrict__ hi,
                            __nv_bfloat16* __restrict__ lo, int rows, int scols, int sld, int dld) {
    long idx = (long)blockIdx.x * 256 + threadIdx.x;
    if (idx >= (long)rows * dld) return;
    int r = idx / dld, c = idx - (long)r * dld;
    float v = (c < scols) ? src[(long)r * sld + c] : 0.f;
    __nv_bfloat16 h = __float2bfloat16(v);
    hi[idx] = h;
    lo[idx] = __float2bfloat16(v - __bfloat162float(h));
}

// ---------------- ctx transpose + split: [b][t][d] -> [b][d][t] ----------------
__global__ void tconv_kernel(const float* __restrict__ src, __nv_bfloat16* __restrict__ hi,
                             __nv_bfloat16* __restrict__ lo) {
    __shared__ float tile[32][33];
    int z = blockIdx.z, t0 = blockIdx.x * 32, d0 = blockIdx.y * 32;
    int tx = threadIdx.x, ty = threadIdx.y;
#pragma unroll
    for (int i = 0; i < 4; i++)
        tile[ty + i*8][tx] = src[((long)z*T_ + t0 + ty + i*8) * D_ + d0 + tx];
    __syncthreads();
#pragma unroll
    for (int i = 0; i < 4; i++) {
        float v = tile[tx][ty + i*8];
        long o = ((long)z*D_ + d0 + ty + i*8) * T_ + t0 + tx;
        __nv_bfloat16 h = __float2bfloat16(v);
        hi[o] = h; lo[o] = __float2bfloat16(v - __bfloat162float(h));
    }
}

__global__ void bsum_kernel(const float* a, const float* b, const float* a2, const float* b2) {
    int i = blockIdx.x * 256 + threadIdx.x;
    if (i < G_) { g_bsum_f[i] = a[i] + b[i]; g_bsum_b[i] = a2[i] + b2[i]; }
}

// ---------------- split-bf16 tensor-core GEMM (mma.sync, baseline PTX) ----------------
struct GemmP {
    const __nv_bfloat16 *Ah[2], *Al[2], *Bh[2], *Bl[2];
    int K[2], lda[2], ldb[2];
    long sA[2], sB[2];
    int nt;
    float* C; int ldc; long sC;
    const float* bias;
    __nv_bfloat16 *Chi, *Clo; int ldhl; long sHL;
};

#define SROW   40
#define TILEB  (128*SROW*2)
#define STAGEB (4*TILEB)
#define GEMM_SMEM (2*STAGEB)

__device__ __forceinline__ uint32_t smem_u32_of(const void* p) {
    uint32_t a;
    asm("{ .reg .u64 t; cvta.to.shared.u64 t, %1; cvt.u32.u64 %0, t; }" : "=r"(a) : "l"(p));
    return a;
}
__device__ __forceinline__ void cpasync16(uint32_t s, const void* g) {
    asm volatile("cp.async.cg.shared.global [%0], [%1], 16;" :: "r"(s), "l"(g));
}
__device__ __forceinline__ void cpcommit() { asm volatile("cp.async.commit_group;"); }
template<int N> __device__ __forceinline__ void cpwait() {
    asm volatile("cp.async.wait_group %0;" :: "n"(N));
}

#define MMA16816(d, a, b0v, b1v) \
    asm volatile("mma.sync.aligned.m16n8k16.row.col.f32.bf16.bf16.f32 " \
        "{%0,%1,%2,%3}, {%4,%5,%6,%7}, {%8,%9}, {%0,%1,%2,%3};" \
        : "+f"((d)[0]), "+f"((d)[1]), "+f"((d)[2]), "+f"((d)[3]) \
        : "r"((a)[0]), "r"((a)[1]), "r"((a)[2]), "r"((a)[3]), "r"(b0v), "r"(b1v))

__device__ __forceinline__ void issue_stage(
    const GemmP& P, int z, int c, int nc0, int buf,
    int tid, int bm, int bn, uint32_t sbase)
{
    int t  = (c < nc0) ? 0 : 1;
    int ch = (c < nc0) ? c : (c - nc0);
    const __nv_bfloat16* Ah = P.Ah[t] + (long)z * P.sA[t];
    const __nv_bfloat16* Al = P.Al[t] + (long)z * P.sA[t];
    const __nv_bfloat16* Bh = P.Bh[t] + (long)z * P.sB[t];
    const __nv_bfloat16* Bl = P.Bl[t] + (long)z * P.sB[t];
    int lda = P.lda[t], ldb = P.ldb[t];
    int kb0 = ch * 32;
#pragma unroll
    for (int i = 0; i < 8; i++) {
        int idx  = i * 256 + tid;
        int tile = idx >> 9;
        int cc   = idx & 511;
        int row  = cc >> 2;
        int seg  = cc & 3;
        uint32_t sa = sbase + buf * STAGEB + tile * TILEB + (row * SROW + seg * 8) * 2;
        int kb = kb0 + seg * 8;
        const __nv_bfloat16* src;
        if      (tile == 0) src = Ah + (long)(bm + row) * lda + kb;
        else if (tile == 1) src = Al + (long)(bm + row) * lda + kb;
        else if (tile == 2) src = Bh + (long)(bn + row) * ldb + kb;
        else                src = Bl + (long)(bn + row) * ldb + kb;
        cpasync16(sa, src);
    }
    cpcommit();
}

template<bool TANH, bool WF32, bool WBF16>
__global__ void __launch_bounds__(256, 2) mma_gemm_kernel(GemmP P) {
    extern __shared__ __align__(16) char smem[];
    const int tid = threadIdx.x, lane = tid & 31, wid = tid >> 5;
    const int g = lane >> 2, tg = lane & 3;
    const int wm = (wid & 3) * 32, wn = (wid >> 2) * 64;
    const int bn = blockIdx.x * 128, bm = blockIdx.y * 128, z = blockIdx.z;
    const uint32_t sbase = smem_u32_of(smem);

    float acc[2][8][4];
#pragma unroll
    for (int mt = 0; mt < 2; mt++)
#pragma unroll
        for (int nt = 0; nt < 8; nt++)
#pragma unroll
            for (int r = 0; r < 4; r++) acc[mt][nt][r] = 0.f;

    const int nc0 = P.K[0] >> 5;
    const int nct = nc0 + ((P.nt > 1) ? (P.K[1] >> 5) : 0);

    issue_stage(P, z, 0, nc0, 0, tid, bm, bn, sbase);

    for (int c = 0; c < nct; c++) {
        int buf = c & 1;
        if (c + 1 < nct) { issue_stage(P, z, c + 1, nc0, buf ^ 1, tid, bm, bn, sbase); cpwait<1>(); }
        else             { cpwait<0>(); }
        __syncthreads();

        const __nv_bfloat16* Ash = (const __nv_bfloat16*)(smem + buf * STAGEB);
        const __nv_bfloat16* Asl = Ash + 128 * SROW;
        const __nv_bfloat16* Bsh = Asl + 128 * SROW;
        const __nv_bfloat16* Bsl = Bsh + 128 * SROW;

#pragma unroll
        for (int s = 0; s < 2; s++) {
            int k0 = s * 16;
            uint32_t ah[2][4], al[2][4];
#pragma unroll
            for (int mt = 0; mt < 2; mt++) {
                int r = wm + mt * 16 + g;
                ah[mt][0] = *(const uint32_t*)&Ash[(r    ) * SROW + k0     + tg * 2];
                ah[mt][1] = *(const uint32_t*)&Ash[(r + 8) * SROW + k0     + tg * 2];
                ah[mt][2] = *(const uint32_t*)&Ash[(r    ) * SROW + k0 + 8 + tg * 2];
                ah[mt][3] = *(const uint32_t*)&Ash[(r + 8) * SROW + k0 + 8 + tg * 2];
                al[mt][0] = *(const uint32_t*)&Asl[(r    ) * SROW + k0     + tg * 2];
                al[mt][1] = *(const uint32_t*)&Asl[(r + 8) * SROW + k0     + tg * 2];
                al[mt][2] = *(const uint32_t*)&Asl[(r    ) * SROW + k0 + 8 + tg * 2];
                al[mt][3] = *(const uint32_t*)&Asl[(r + 8) * SROW + k0 + 8 + tg * 2];
            }
#pragma unroll
            for (int nt = 0; nt < 8; nt++) {
                int n = wn + nt * 8 + g;
                uint32_t bh0 = *(const uint32_t*)&Bsh[n * SROW + k0     + tg * 2];
                uint32_t bh1 = *(const uint32_t*)&Bsh[n * SROW + k0 + 8 + tg * 2];
                uint32_t bl0 = *(const uint32_t*)&Bsl[n * SROW + k0     + tg * 2];
                uint32_t bl1 = *(const uint32_t*)&Bsl[n * SROW + k0 + 8 + tg * 2];
#pragma unroll
                for (int mt = 0; mt < 2; mt++) {
                    MMA16816(acc[mt][nt], ah[mt], bh0, bh1);
                    MMA16816(acc[mt][nt], ah[mt], bl0, bl1);
                    MMA16816(acc[mt][nt], al[mt], bh0, bh1);
                }
            }
        }
        __syncthreads();
    }

#pragma unroll
    for (int mt = 0; mt < 2; mt++) {
#pragma unroll
        for (int nt = 0; nt < 8; nt++) {
            int col = bn + wn + nt * 8 + tg * 2;
            float bv0 = P.bias ? P.bias[col]     : 0.f;
            float bv1 = P.bias ? P.bias[col + 1] : 0.f;
#pragma unroll
            for (int h = 0; h < 2; h++) {
                int row = bm + wm + mt * 16 + g + h * 8;
                float v0 = acc[mt][nt][h * 2]     + bv0;
                float v1 = acc[mt][nt][h * 2 + 1] + bv1;
                if (TANH) { v0 = tanhf(v0); v1 = tanhf(v1); }
                if (WF32) {
                    float* cp = P.C + (long)z * P.sC + (long)row * P.ldc + col;
                    cp[0] = v0; cp[1] = v1;
                }
                if (WBF16) {
                    long o = (long)z * P.sHL + (long)row * P.ldhl + col;
                    __nv_bfloat16 h0 = __float2bfloat16(v0);
                    __nv_bfloat16 h1 = __float2bfloat16(v1);
                    P.Chi[o] = h0; P.Chi[o + 1] = h1;
                    P.Clo[o]     = __float2bfloat16(v0 - __bfloat162float(h0));
                    P.Clo[o + 1] = __float2bfloat16(v1 - __bfloat162float(h1));
                }
            }
        }
    }
}

// ---------------- persistent bidirectional LSTM (3-pass, chunk-pipelined h stage) ----------------
__device__ __forceinline__ void gbar_arrive(int dir) {
    __threadfence();
    __syncthreads();
    if (threadIdx.x == 0) atomicAdd(&g_barA[dir * 8], 1u);
}
__device__ __forceinline__ void gbar_wait(int dir, unsigned bc) {
    if (threadIdx.x == 0) {
        unsigned target = bc * 64u;
        while (*((volatile unsigned*)&g_barA[dir * 8]) < target) { __nanosleep(32); }
        __threadfence();
    }
    __syncthreads();
}
__global__ void reset_kernel() { g_barA[0] = 0u; g_barA[8] = 0u; }

// smem layout (bytes): WS hi/lo [32][520], HS hi/lo [64][520], SG [64][33]
#define LS_WS_H 0
#define LS_WS_L 33280
#define LS_HS_H 66560
#define LS_HS_L 133120
#define LS_SG   199680
#define LSTM_SMEM (199680 + 64*33*4)

// stage one K-chunk (128 k = segs [16*ch, 16*ch+16)) of h hi+lo into smem
__device__ __forceinline__ void lstm_stage_chunk(
    const __nv_bfloat16* Hh, const __nv_bfloat16* Hl,
    uint32_t sbase, int ch, int tid)
{
    for (int c2 = tid; c2 < 2048; c2 += 256) {
        int arr = c2 >> 10;            // 0 = hi, 1 = lo
        int cc  = c2 & 1023;
        int row = cc >> 4;
        int seg = (cc & 15) + ch * 16;
        uint32_t sa = sbase + (arr ? LS_HS_L : LS_HS_H) + row * 1040 + seg * 16;
        const __nv_bfloat16* src = (arr ? Hl : Hh) + row * H_ + seg * 8;
        cpasync16(sa, src);
    }
    cpcommit();
}

// 128 blocks = 2 dirs x 64. Block owns 8 hidden units (32 gate-cols) over full K=512.
__global__ void __launch_bounds__(256, 1) lstm_kernel(
    const float* __restrict__ whf, const float* __restrict__ whb)
{
    extern __shared__ __align__(16) char smem[];
    __nv_bfloat16* WS_h = (__nv_bfloat16*)(smem + LS_WS_H);
    __nv_bfloat16* WS_l = (__nv_bfloat16*)(smem + LS_WS_L);
    __nv_bfloat16* HS_h = (__nv_bfloat16*)(smem + LS_HS_H);
    __nv_bfloat16* HS_l = (__nv_bfloat16*)(smem + LS_HS_L);
    float* SG = (float*)(smem + LS_SG);          // [64][33] gate sums
    const uint32_t sbase = smem_u32_of(smem);

    const int tid = threadIdx.x, lane = tid & 31, wid = tid >> 5;
    const int g = lane >> 2, tg = lane & 3;
    const int bid = blockIdx.x;
    const int dir = bid >> 6, b64 = bid & 63;
    const float* W    = dir ? whb : whf;           // [2048][512]
    const float* xpre = dir ? g_xpre_b : g_xpre_f;

    // preload W slice: rows r = gate*8 + j  (gate-col = gate*512 + b64*8 + j), split bf16
    for (int idx = tid; idx < 32 * 512; idx += 256) {
        int r = idx >> 9, k = idx & 511;
        int gg = r >> 3, j = r & 7;
        float v = W[(long)(gg * H_ + b64 * 8 + j) * H_ + k];
        __nv_bfloat16 h = __float2bfloat16(v);
        WS_h[r * 520 + k] = h;
        WS_l[r * 520 + k] = __float2bfloat16(v - __bfloat162float(h));
    }
    __syncthreads();

    const int m0 = (wid & 3) * 16, n0 = (wid >> 2) * 16;   // 8 warps: 4m x 2n
    const int v0 = tid * 2;
    const int ub0 = v0 >> 3, uj0 = v0 & 7;
    const int col0 = b64 * 8 + uj0;
    float creg0 = 0.f, creg1 = 0.f;
    unsigned bc = 0;

    for (int s = 0; s < T_; s++) {
        int t = dir ? (T_ - 1 - s) : s;
        int wbuf = s & 1, rbuf = wbuf ^ 1;

        // prefetch xpre gates (independent of h) BEFORE the barrier wait
        float xg0[4], xg1[4];
        {
            const float* xp = xpre + ((long)ub0 * T_ + t) * G_ + b64 * 8 + uj0;
#pragma unroll
            for (int q = 0; q < 4; q++) { xg0[q] = __ldcg(&xp[q * H_]); xg1[q] = __ldcg(&xp[q * H_ + 1]); }
        }

        if (s > 0) {
            gbar_wait(dir, bc);   // all dir-peers finished step s-1 (h written + fenced)

            const __nv_bfloat16* Hh = g_hhi[dir][rbuf];
            const __nv_bfloat16* Hl = g_hlo[dir][rbuf];

            float acc[2][4];
#pragma unroll
            for (int nt = 0; nt < 2; nt++)
#pragma unroll
                for (int r = 0; r < 4; r++) acc[nt][r] = 0.f;

            // chunk-pipelined: stage chunk c+1 while MMA-ing chunk c
            lstm_stage_chunk(Hh, Hl, sbase, 0, tid);
#pragma unroll
            for (int chk = 0; chk < 4; chk++) {
                if (chk < 3) { lstm_stage_chunk(Hh, Hl, sbase, chk + 1, tid); cpwait<1>(); }
                else         { cpwait<0>(); }
                __syncthreads();

#pragma unroll
                for (int kss = 0; kss < 8; kss++) {
                    int kw = (chk * 8 + kss) * 16;
                    uint32_t ah[4], al[4];
                    ah[0] = *(const uint32_t*)&HS_h[(m0 + g    ) * 520 + kw     + tg * 2];
                    ah[1] = *(const uint32_t*)&HS_h[(m0 + g + 8) * 520 + kw     + tg * 2];
                    ah[2] = *(const uint32_t*)&HS_h[(m0 + g    ) * 520 + kw + 8 + tg * 2];
                    ah[3] = *(const uint32_t*)&HS_h[(m0 + g + 8) * 520 + kw + 8 + tg * 2];
                    al[0] = *(const uint32_t*)&HS_l[(m0 + g    ) * 520 + kw     + tg * 2];
                    al[1] = *(const uint32_t*)&HS_l[(m0 + g + 8) * 520 + kw     + tg * 2];
                    al[2] = *(const uint32_t*)&HS_l[(m0 + g    ) * 520 + kw + 8 + tg * 2];
                    al[3] = *(const uint32_t*)&HS_l[(m0 + g + 8) * 520 + kw + 8 + tg * 2];
#pragma unroll
                    for (int nt = 0; nt < 2; nt++) {
                        int n = n0 + nt * 8 + g;
                        uint32_t bh0 = *(const uint32_t*)&WS_h[n * 520 + kw     + tg * 2];
                        uint32_t bh1 = *(const uint32_t*)&WS_h[n * 520 + kw + 8 + tg * 2];
                        uint32_t bl0 = *(const uint32_t*)&WS_l[n * 520 + kw     + tg * 2];
                        uint32_t bl1 = *(const uint32_t*)&WS_l[n * 520 + kw + 8 + tg * 2];
                        MMA16816(acc[nt], ah, bh0, bh1);
                        MMA16816(acc[nt], ah, bl0, bl1);
                        MMA16816(acc[nt], al, bh0, bh1);
                    }
                }
            }
#pragma unroll
            for (int nt = 0; nt < 2; nt++) {
                int col = n0 + nt * 8 + tg * 2;
                SG[(m0 + g    ) * 33 + col    ] = acc[nt][0];
                SG[(m0 + g    ) * 33 + col + 1] = acc[nt][1];
                SG[(m0 + g + 8) * 33 + col    ] = acc[nt][2];
                SG[(m0 + g + 8) * 33 + col + 1] = acc[nt][3];
            }
            __syncthreads();
        }

        // cell update (2 values per thread)
        {
            float gv0[4], gv1[4];
#pragma unroll
            for (int q = 0; q < 4; q++) {
                float a0 = xg0[q], a1 = xg1[q];
                if (s > 0) {
                    a0 += SG[ub0 * 33 + q * 8 + uj0];
                    a1 += SG[ub0 * 33 + q * 8 + uj0 + 1];
                }
                gv0[q] = a0; gv1[q] = a1;
            }
            float i0 = 1.f / (1.f + expf(-gv0[0]));
            float f0 = 1.f / (1.f + expf(-gv0[1]));
            float c0 = tanhf(gv0[2]);
            float o0 = 1.f / (1.f + expf(-gv0[3]));
            creg0 = f0 * creg0 + i0 * c0;
            float h0 = o0 * tanhf(creg0);

            float i1 = 1.f / (1.f + expf(-gv1[0]));
            float f1 = 1.f / (1.f + expf(-gv1[1]));
            float c1 = tanhf(gv1[2]);
            float o1 = 1.f / (1.f + expf(-gv1[3]));
            creg1 = f1 * creg1 + i1 * c1;
            float h1 = o1 * tanhf(creg1);

            long co = ((long)ub0 * T_ + t) * D_ + dir * H_ + col0;
            __nv_bfloat16 hh0 = __float2bfloat16(h0);
            __nv_bfloat16 hh1 = __float2bfloat16(h1);
            __nv_bfloat16 hl0 = __float2bfloat16(h0 - __bfloat162float(hh0));
            __nv_bfloat16 hl1 = __float2bfloat16(h1 - __bfloat162float(hh1));
            g_ctx[co]     = h0;
            g_ctx[co + 1] = h1;
            g_ch[co] = hh0; g_ch[co + 1] = hh1;     // ctx split emitted in-scan
            g_cl[co] = hl0; g_cl[co + 1] = hl1;
            __nv_bfloat16* Hh = g_hhi[dir][wbuf];
            __nv_bfloat16* Hl = g_hlo[dir][wbuf];
            Hh[ub0 * H_ + col0]     = hh0;
            Hh[ub0 * H_ + col0 + 1] = hh1;
            Hl[ub0 * H_ + col0]     = hl0;
            Hl[ub0 * H_ + col0 + 1] = hl1;
        }
        gbar_arrive(dir); ++bc;
    }
}

// ---------------- softmax (fused attn hi/lo emit) / mean / head / bn ----------------
__global__ void softmax_kernel(const unsigned char* __restrict__ mask) {
    int row = blockIdx.x;
    int tid = threadIdx.x;
    int b = row >> 8;
    float v = g_scores[(long)row * T_ + tid];
    if (mask[b * T_ + tid]) v = -INFINITY;
    __shared__ float red[256];
    red[tid] = v; __syncthreads();
    for (int s = 128; s > 0; s >>= 1) {
        if (tid < s) red[tid] = fmaxf(red[tid], red[tid + s]);
        __syncthreads();
    }
    float m = red[0]; __syncthreads();
    float e = __expf(v - m);
    red[tid] = e; __syncthreads();
    for (int s = 128; s > 0; s >>= 1) {
        if (tid < s) red[tid] += red[tid + s];
        __syncthreads();
    }
    float a = e / red[0];
    long o = (long)row * T_ + tid;
    __nv_bfloat16 h = __float2bfloat16(a);
    g_ah[o] = h;
    g_al[o] = __float2bfloat16(a - __bfloat162float(h));
}

__global__ void mean_kernel() {
    int idx = blockIdx.x * 256 + threadIdx.x;
    int b = idx >> 10, d = idx & 1023;
    const float* p = &g_htilde[(long)b * T_ * D_ + d];
    float s = 0.f;
    for (int t = 0; t < T_; t++) s += p[(long)t * D_];
    g_ctxout[idx] = s * (1.0f / T_);
}

__global__ void yhead_kernel(const float* __restrict__ w_out, const float* __restrict__ b_out) {
    int m = blockIdx.x, tid = threadIdx.x;
    int wid = tid >> 5, lid = tid & 31;
    const float* x = &g_ctxout[m * D_];
    for (int n = wid; n < OUT_; n += 8) {
        const float* w = &w_out[(long)n * D_];
        float s = 0.f;
        for (int k = lid; k < D_; k += 32) s += x[k] * w[k];
#pragma unroll
        for (int o = 16; o > 0; o >>= 1) s += __shfl_down_sync(0xffffffffu, s, o);
        if (lid == 0) g_y[m * OUT_ + n] = tanhf(s + b_out[n]);
    }
}

__global__ void bn_kernel(const float* __restrict__ gamma, const float* __restrict__ beta,
                          float* __restrict__ out) {
    int n = threadIdx.x;
    float mu = 0.f;
    for (int b = 0; b < B_; b++) mu += g_y[b * OUT_ + n];
    mu *= (1.0f / B_);
    float var = 0.f;
    for (int b = 0; b < B_; b++) { float d = g_y[b * OUT_ + n] - mu; var += d * d; }
    var *= (1.0f / B_);
    float inv = rsqrtf(var + 1e-5f);
    float ga = gamma[n], be = beta[n];
    for (int b = 0; b < B_; b++)
        out[b * OUT_ + n] = ga * (g_y[b * OUT_ + n] - mu) * inv + be;
}

// ---------------- host launcher ----------------
static inline void conv(const float* s, __nv_bfloat16* h, __nv_bfloat16* l,
                        int rows, int scols, int sld, int dld) {
    long tot = (long)rows * dld;
    conv_kernel<<<(unsigned)((tot + 255) / 256), 256>>>(s, h, l, rows, scols, sld, dld);
}

extern "C" void kernel_launch(void* const* d_in, const int* in_sizes, int n_in,
                              void* d_out, int out_size) {
    const int*   inputs = (const int*)d_in[0];
    const unsigned char* mask = (const unsigned char*)d_in[1];
    const float* table  = (const float*)d_in[2];
    const float* w_ih_f = (const float*)d_in[3];
    const float* w_hh_f = (const float*)d_in[4];
    const float* b_ih_f = (const float*)d_in[5];
    const float* b_hh_f = (const float*)d_in[6];
    const float* w_ih_b = (const float*)d_in[7];
    const float* w_hh_b = (const float*)d_in[8];
    const float* b_ih_b = (const float*)d_in[9];
    const float* b_hh_b = (const float*)d_in[10];
    const float* w_in   = (const float*)d_in[11];
    const float* w_attn = (const float*)d_in[12];
    const float* w_out  = (const float*)d_in[13];
    const float* b_out  = (const float*)d_in[14];
    const float* gamma  = (const float*)d_in[15];
    const float* beta   = (const float*)d_in[16];
    float* out = (float*)d_out;

    float *embeds, *xf, *xb, *ctx, *scores, *htilde, *bsf, *bsb;
    cudaGetSymbolAddress((void**)&embeds, g_embeds);
    cudaGetSymbolAddress((void**)&xf,     g_xpre_f);
    cudaGetSymbolAddress((void**)&xb,     g_xpre_b);
    cudaGetSymbolAddress((void**)&ctx,    g_ctx);
    cudaGetSymbolAddress((void**)&scores, g_scores);
    cudaGetSymbolAddress((void**)&htilde, g_htilde);
    cudaGetSymbolAddress((void**)&bsf,    g_bsum_f);
    cudaGetSymbolAddress((void**)&bsb,    g_bsum_b);
    __nv_bfloat16 *eh,*el,*wfh,*wfl,*wbh,*wbl,*ch,*cl,*cth,*ctl,*winh,*winl,
                  *th,*tl,*ah,*al,*w1h,*w1l,*w2h,*w2l,*wh,*wl;
    cudaGetSymbolAddress((void**)&eh, g_eh);   cudaGetSymbolAddress((void**)&el, g_el);
    cudaGetSymbolAddress((void**)&wfh, g_wfh); cudaGetSymbolAddress((void**)&wfl, g_wfl);
    cudaGetSymbolAddress((void**)&wbh, g_wbh); cudaGetSymbolAddress((void**)&wbl, g_wbl);
    cudaGetSymbolAddress((void**)&ch, g_ch);   cudaGetSymbolAddress((void**)&cl, g_cl);
    cudaGetSymbolAddress((void**)&cth, g_cth); cudaGetSymbolAddress((void**)&ctl, g_ctl);
    cudaGetSymbolAddress((void**)&winh, g_winh); cudaGetSymbolAddress((void**)&winl, g_winl);
    cudaGetSymbolAddress((void**)&th, g_th);   cudaGetSymbolAddress((void**)&tl, g_tl);
    cudaGetSymbolAddress((void**)&ah, g_ah);   cudaGetSymbolAddress((void**)&al, g_al);
    cudaGetSymbolAddress((void**)&w1h, g_w1h); cudaGetSymbolAddress((void**)&w1l, g_w1l);
    cudaGetSymbolAddress((void**)&w2h, g_w2h); cudaGetSymbolAddress((void**)&w2l, g_w2l);
    cudaGetSymbolAddress((void**)&wh, g_wh);   cudaGetSymbolAddress((void**)&wl, g_wl);

    cudaFuncSetAttribute(mma_gemm_kernel<false,true,false>,
                         cudaFuncAttributeMaxDynamicSharedMemorySize, GEMM_SMEM);
    cudaFuncSetAttribute(mma_gemm_kernel<false,false,true>,
                         cudaFuncAttributeMaxDynamicSharedMemorySize, GEMM_SMEM);
    cudaFuncSetAttribute(mma_gemm_kernel<true,true,false>,
                         cudaFuncAttributeMaxDynamicSharedMemorySize, GEMM_SMEM);

    // 1. embed + operand conversions
    embed_kernel<<<(BT_*E_ + 255) / 256, 256>>>(inputs, table);
    conv(embeds, eh, el, BT_, E_, E_, EP_);
    conv(w_ih_f, wfh, wfl, G_, E_, E_, EP_);
    conv(w_ih_b, wbh, wbl, G_, E_, E_, EP_);
    conv(w_in,   winh, winl, D_, D_, D_, D_);
    conv(w_attn,        w1h, w1l, D_, D_, 2*D_, D_);
    conv(w_attn + D_,   w2h, w2l, D_, D_, 2*D_, D_);
    bsum_kernel<<<(G_ + 255) / 256, 256>>>(b_ih_f, b_hh_f, b_ih_b, b_hh_b);

    // 2. xpre = embeds @ w_ih^T + (b_ih + b_hh)
    {
        GemmP P{};
        P.nt = 1; P.K[0] = EP_; P.lda[0] = EP_; P.ldb[0] = EP_;
        P.Ah[0] = eh; P.Al[0] = el; P.ldc = G_;
        P.Bh[0] = wfh; P.Bl[0] = wfl; P.C = xf; P.bias = bsf;
        dim3 g(G_/128, BT_/128, 1);
        mma_gemm_kernel<false,true,false><<<g, 256, GEMM_SMEM>>>(P);
        P.Bh[0] = wbh; P.Bl[0] = wbl; P.C = xb; P.bias = bsb;
        mma_gemm_kernel<false,true,false><<<g, 256, GEMM_SMEM>>>(P);
    }

    // 3. persistent bidirectional LSTM (chunk-pipelined stage; emits ctx fp32 + split)
    reset_kernel<<<1, 1>>>();
    cudaFuncSetAttribute(lstm_kernel, cudaFuncAttributeMaxDynamicSharedMemorySize, LSTM_SMEM);
    lstm_kernel<<<NB_LSTM, 256, LSTM_SMEM>>>(w_hh_f, w_hh_b);

    // 4. ctx transposed split only (plain split produced by the LSTM)
    tconv_kernel<<<dim3(T_/32, D_/32, B_), dim3(32, 8)>>>(ctx, cth, ctl);

    // 5. target = ctx @ w_in^T  (bf16 hi/lo out)
    {
        GemmP P{};
        P.nt = 1; P.K[0] = D_; P.lda[0] = D_; P.ldb[0] = D_;
        P.Ah[0] = ch; P.Al[0] = cl; P.Bh[0] = winh; P.Bl[0] = winl;
        P.Chi = th; P.Clo = tl; P.ldhl = D_;
        dim3 g(D_/128, BT_/128, 1);
        mma_gemm_kernel<false,false,true><<<g, 256, GEMM_SMEM>>>(P);
    }

    // 6. scores[z] = target[z] @ ctx[z]^T  (fp32 out)
    {
        GemmP P{};
        P.nt = 1; P.K[0] = D_; P.lda[0] = D_; P.ldb[0] = D_;
        P.Ah[0] = th; P.Al[0] = tl; P.sA[0] = (long)T_*D_;
        P.Bh[0] = ch; P.Bl[0] = cl; P.sB[0] = (long)T_*D_;
        P.C = scores; P.ldc = T_; P.sC = (long)T_*T_;
        dim3 g(T_/128, T_/128, B_);
        mma_gemm_kernel<false,true,false><<<g, 256, GEMM_SMEM>>>(P);
    }

    // 7. softmax (emits attn bf16 hi/lo directly)
    softmax_kernel<<<BT_, 256>>>(mask);

    // 8. weighted[z] = attn[z] @ ctxT[z]^T  (bf16 hi/lo out)
    {
        GemmP P{};
        P.nt = 1; P.K[0] = T_; P.lda[0] = T_; P.ldb[0] = T_;
        P.Ah[0] = ah; P.Al[0] = al; P.sA[0] = (long)T_*T_;
        P.Bh[0] = cth; P.Bl[0] = ctl; P.sB[0] = (long)D_*T_;
        P.Chi = wh; P.Clo = wl; P.ldhl = D_; P.sHL = (long)T_*D_;
        dim3 g(D_/128, T_/128, B_);
        mma_gemm_kernel<false,false,true><<<g, 256, GEMM_SMEM>>>(P);
    }

    // 9. htilde = tanh(weighted @ W1^T + ctx @ W2^T)
    {
        GemmP P{};
        P.nt = 2;
        P.K[0] = D_; P.lda[0] = D_; P.ldb[0] = D_;
        P.Ah[0] = wh; P.Al[0] = wl; P.Bh[0] = w1h; P.Bl[0] = w1l;
        P.K[1] = D_; P.lda[1] = D_; P.ldb[1] = D_;
        P.Ah[1] = ch; P.Al[1] = cl; P.Bh[1] = w2h; P.Bl[1] = w2l;
        P.C = htilde; P.ldc = D_;
        dim3 g(D_/128, BT_/128, 1);
        mma_gemm_kernel<true,true,false><<<g, 256, GEMM_SMEM>>>(P);
    }

    // 10-12. mean, head, batchnorm
    mean_kernel<<<(B_*D_)/256, 256>>>();
    yhead_kernel<<<B_, 256>>>(w_out, b_out);
    bn_kernel<<<1, OUT_>>>(gamma, beta, out);
}

// round 16
// speedup vs baseline: 1.3502x; 1.1495x over previous
#include <cuda_runtime.h>
#include <cuda_bf16.h>
#include <cuda_fp16.h>
#include <cstdint>
#include <math.h>

#define B_   64
#define T_   256
#define E_   300
#define EP_  320
#define H_   512
#define D_   1024
#define G_   2048
#define OUT_ 256
#define NB_LSTM 128u
#define BT_  (B_*T_)

// ---------------- fp32 scratch ----------------
__device__ float g_embeds[BT_*E_];
__device__ float g_xpre_f[BT_*G_];
__device__ float g_xpre_b[BT_*G_];
__device__ float g_ctx[BT_*D_];
__device__ float g_scores[BT_*T_];
__device__ float g_htilde[BT_*D_];
__device__ float g_ctxout[B_*D_];
__device__ float g_y[B_*OUT_];
__device__ float g_bsum_f[G_];
__device__ float g_bsum_b[G_];
__device__ unsigned g_barA[16];    // two per-direction counters, 32B apart

// LSTM recurrent h, fp16, double-buffered: [dir][buf][64*512]
__device__ __align__(16) __half g_hfp[2][2][B_*H_];

// ---------------- bf16 hi/lo scratch (16B aligned) ----------------
__device__ __align__(16) __nv_bfloat16 g_eh[BT_*EP_],   g_el[BT_*EP_];
__device__ __align__(16) __nv_bfloat16 g_wfh[G_*EP_],   g_wfl[G_*EP_];
__device__ __align__(16) __nv_bfloat16 g_wbh[G_*EP_],   g_wbl[G_*EP_];
__device__ __align__(16) __nv_bfloat16 g_ch[BT_*D_],    g_cl[BT_*D_];
__device__ __align__(16) __nv_bfloat16 g_cth[B_*D_*T_], g_ctl[B_*D_*T_];
__device__ __align__(16) __nv_bfloat16 g_winh[D_*D_],   g_winl[D_*D_];
__device__ __align__(16) __nv_bfloat16 g_th[BT_*D_],    g_tl[BT_*D_];
__device__ __align__(16) __nv_bfloat16 g_ah[BT_*T_],    g_al[BT_*T_];
__device__ __align__(16) __nv_bfloat16 g_w1h[D_*D_],    g_w1l[D_*D_];
__device__ __align__(16) __nv_bfloat16 g_w2h[D_*D_],    g_w2l[D_*D_];
__device__ __align__(16) __nv_bfloat16 g_wh[BT_*D_],    g_wl[BT_*D_];

// ---------------- embedding ----------------
__global__ void embed_kernel(const int* __restrict__ inp, const float* __restrict__ table) {
    int idx = blockIdx.x * blockDim.x + threadIdx.x;
    if (idx >= BT_*E_) return;
    int bt = idx / E_, e = idx - bt * E_;
    g_embeds[idx] = table[(long)inp[bt] * E_ + e];
}

__device__ __forceinline__ void split_write(float v, __nv_bfloat16* hi, __nv_bfloat16* lo, long o) {
    __nv_bfloat16 h = __float2bfloat16(v);
    hi[o] = h;
    lo[o] = __float2bfloat16(v - __bfloat162float(h));
}

// fused pre-LSTM conversions: embeds, w_ih_f, w_ih_b (K-padded), bias sums
__global__ void preconv_kernel(const float* __restrict__ wf, const float* __restrict__ wb,
                               const float* __restrict__ bif, const float* __restrict__ bhf,
                               const float* __restrict__ bib, const float* __restrict__ bhb) {
    long idx = (long)blockIdx.x * 256 + threadIdx.x;
    const long N0 = (long)BT_ * EP_, N1 = (long)G_ * EP_;
    if (idx < N0) {
        int r = idx / EP_, c = idx - (long)r * EP_;
        float v = (c < E_) ? g_embeds[(long)r * E_ + c] : 0.f;
        split_write(v, g_eh, g_el, idx);
    } else if (idx < N0 + N1) {
        long i = idx - N0;
        int r = i / EP_, c = i - (long)r * EP_;
        float v = (c < E_) ? wf[(long)r * E_ + c] : 0.f;
        split_write(v, g_wfh, g_wfl, i);
    } else if (idx < N0 + 2*N1) {
        long i = idx - N0 - N1;
        int r = i / EP_, c = i - (long)r * EP_;
        float v = (c < E_) ? wb[(long)r * E_ + c] : 0.f;
        split_write(v, g_wbh, g_wbl, i);
    } else if (idx < N0 + 2*N1 + G_) {
        int i = (int)(idx - N0 - 2*N1);
        g_bsum_f[i] = bif[i] + bhf[i];
        g_bsum_b[i] = bib[i] + bhb[i];
    }
}

// fused post-LSTM weight conversions: w_in, w_attn halves
__global__ void postconv_kernel(const float* __restrict__ w_in, const float* __restrict__ w_attn) {
    long idx = (long)blockIdx.x * 256 + threadIdx.x;
    const long N = (long)D_ * D_;
    if (idx < N) {
        int r = idx / D_, c = idx - (long)r * D_;
        split_write(w_in[(long)r * D_ + c], g_winh, g_winl, idx);
    } else if (idx < 2*N) {
        long i = idx - N;
        int r = i / D_, c = i - (long)r * D_;
        split_write(w_attn[(long)r * 2*D_ + c], g_w1h, g_w1l, i);
    } else if (idx < 3*N) {
        long i = idx - 2*N;
        int r = i / D_, c = i - (long)r * D_;
        split_write(w_attn[(long)r * 2*D_ + D_ + c], g_w2h, g_w2l, i);
    }
}

// ---------------- ctx transpose + split: [b][t][d] -> [b][d][t] ----------------
__global__ void tconv_kernel(const float* __restrict__ src, __nv_bfloat16* __restrict__ hi,
                             __nv_bfloat16* __restrict__ lo) {
    __shared__ float tile[32][33];
    int z = blockIdx.z, t0 = blockIdx.x * 32, d0 = blockIdx.y * 32;
    int tx = threadIdx.x, ty = threadIdx.y;
#pragma unroll
    for (int i = 0; i < 4; i++)
        tile[ty + i*8][tx] = src[((long)z*T_ + t0 + ty + i*8) * D_ + d0 + tx];
    __syncthreads();
#pragma unroll
    for (int i = 0; i < 4; i++) {
        float v = tile[tx][ty + i*8];
        long o = ((long)z*D_ + d0 + ty + i*8) * T_ + t0 + tx;
        __nv_bfloat16 h = __float2bfloat16(v);
        hi[o] = h; lo[o] = __float2bfloat16(v - __bfloat162float(h));
    }
}

// ---------------- split-bf16 tensor-core GEMM (mma.sync, baseline PTX) ----------------
struct GemmP {
    const __nv_bfloat16 *Ah[2], *Al[2], *Bh[2], *Bl[2];
    int K[2], lda[2], ldb[2];
    long sA[2], sB[2];
    int nt;
    float* C; int ldc; long sC;
    const float* bias;
    __nv_bfloat16 *Chi, *Clo; int ldhl; long sHL;
};

#define SROW   40
#define TILEB  (128*SROW*2)
#define STAGEB (4*TILEB)
#define GEMM_SMEM (2*STAGEB)

__device__ __forceinline__ uint32_t smem_u32_of(const void* p) {
    uint32_t a;
    asm("{ .reg .u64 t; cvta.to.shared.u64 t, %1; cvt.u32.u64 %0, t; }" : "=r"(a) : "l"(p));
    return a;
}
__device__ __forceinline__ void cpasync16(uint32_t s, const void* g) {
    asm volatile("cp.async.cg.shared.global [%0], [%1], 16;" :: "r"(s), "l"(g));
}
__device__ __forceinline__ void cpcommit() { asm volatile("cp.async.commit_group;"); }
template<int N> __device__ __forceinline__ void cpwait() {
    asm volatile("cp.async.wait_group %0;" :: "n"(N));
}

#define MMA16816(d, a, b0v, b1v) \
    asm volatile("mma.sync.aligned.m16n8k16.row.col.f32.bf16.bf16.f32 " \
        "{%0,%1,%2,%3}, {%4,%5,%6,%7}, {%8,%9}, {%0,%1,%2,%3};" \
        : "+f"((d)[0]), "+f"((d)[1]), "+f"((d)[2]), "+f"((d)[3]) \
        : "r"((a)[0]), "r"((a)[1]), "r"((a)[2]), "r"((a)[3]), "r"(b0v), "r"(b1v))

#define MMAF16(d, a, b0v, b1v) \
    asm volatile("mma.sync.aligned.m16n8k16.row.col.f32.f16.f16.f32 " \
        "{%0,%1,%2,%3}, {%4,%5,%6,%7}, {%8,%9}, {%0,%1,%2,%3};" \
        : "+f"((d)[0]), "+f"((d)[1]), "+f"((d)[2]), "+f"((d)[3]) \
        : "r"((a)[0]), "r"((a)[1]), "r"((a)[2]), "r"((a)[3]), "r"(b0v), "r"(b1v))

__device__ __forceinline__ void issue_stage(
    const GemmP& P, int z, int c, int nc0, int buf,
    int tid, int bm, int bn, uint32_t sbase)
{
    int t  = (c < nc0) ? 0 : 1;
    int ch = (c < nc0) ? c : (c - nc0);
    const __nv_bfloat16* Ah = P.Ah[t] + (long)z * P.sA[t];
    const __nv_bfloat16* Al = P.Al[t] + (long)z * P.sA[t];
    const __nv_bfloat16* Bh = P.Bh[t] + (long)z * P.sB[t];
    const __nv_bfloat16* Bl = P.Bl[t] + (long)z * P.sB[t];
    int lda = P.lda[t], ldb = P.ldb[t];
    int kb0 = ch * 32;
#pragma unroll
    for (int i = 0; i < 8; i++) {
        int idx  = i * 256 + tid;
        int tile = idx >> 9;
        int cc   = idx & 511;
        int row  = cc >> 2;
        int seg  = cc & 3;
        uint32_t sa = sbase + buf * STAGEB + tile * TILEB + (row * SROW + seg * 8) * 2;
        int kb = kb0 + seg * 8;
        const __nv_bfloat16* src;
        if      (tile == 0) src = Ah + (long)(bm + row) * lda + kb;
        else if (tile == 1) src = Al + (long)(bm + row) * lda + kb;
        else if (tile == 2) src = Bh + (long)(bn + row) * ldb + kb;
        else                src = Bl + (long)(bn + row) * ldb + kb;
        cpasync16(sa, src);
    }
    cpcommit();
}

template<bool TANH, bool WF32, bool WBF16>
__global__ void __launch_bounds__(256, 2) mma_gemm_kernel(GemmP P) {
    extern __shared__ __align__(16) char smem[];
    const int tid = threadIdx.x, lane = tid & 31, wid = tid >> 5;
    const int g = lane >> 2, tg = lane & 3;
    const int wm = (wid & 3) * 32, wn = (wid >> 2) * 64;
    const int bn = blockIdx.x * 128, bm = blockIdx.y * 128, z = blockIdx.z;
    const uint32_t sbase = smem_u32_of(smem);

    float acc[2][8][4];
#pragma unroll
    for (int mt = 0; mt < 2; mt++)
#pragma unroll
        for (int nt = 0; nt < 8; nt++)
#pragma unroll
            for (int r = 0; r < 4; r++) acc[mt][nt][r] = 0.f;

    const int nc0 = P.K[0] >> 5;
    const int nct = nc0 + ((P.nt > 1) ? (P.K[1] >> 5) : 0);

    issue_stage(P, z, 0, nc0, 0, tid, bm, bn, sbase);

    for (int c = 0; c < nct; c++) {
        int buf = c & 1;
        if (c + 1 < nct) { issue_stage(P, z, c + 1, nc0, buf ^ 1, tid, bm, bn, sbase); cpwait<1>(); }
        else             { cpwait<0>(); }
        __syncthreads();

        const __nv_bfloat16* Ash = (const __nv_bfloat16*)(smem + buf * STAGEB);
        const __nv_bfloat16* Asl = Ash + 128 * SROW;
        const __nv_bfloat16* Bsh = Asl + 128 * SROW;
        const __nv_bfloat16* Bsl = Bsh + 128 * SROW;

#pragma unroll
        for (int s = 0; s < 2; s++) {
            int k0 = s * 16;
            uint32_t ah[2][4], al[2][4];
#pragma unroll
            for (int mt = 0; mt < 2; mt++) {
                int r = wm + mt * 16 + g;
                ah[mt][0] = *(const uint32_t*)&Ash[(r    ) * SROW + k0     + tg * 2];
                ah[mt][1] = *(const uint32_t*)&Ash[(r + 8) * SROW + k0     + tg * 2];
                ah[mt][2] = *(const uint32_t*)&Ash[(r    ) * SROW + k0 + 8 + tg * 2];
                ah[mt][3] = *(const uint32_t*)&Ash[(r + 8) * SROW + k0 + 8 + tg * 2];
                al[mt][0] = *(const uint32_t*)&Asl[(r    ) * SROW + k0     + tg * 2];
                al[mt][1] = *(const uint32_t*)&Asl[(r + 8) * SROW + k0     + tg * 2];
                al[mt][2] = *(const uint32_t*)&Asl[(r    ) * SROW + k0 + 8 + tg * 2];
                al[mt][3] = *(const uint32_t*)&Asl[(r + 8) * SROW + k0 + 8 + tg * 2];
            }
#pragma unroll
            for (int nt = 0; nt < 8; nt++) {
                int n = wn + nt * 8 + g;
                uint32_t bh0 = *(const uint32_t*)&Bsh[n * SROW + k0     + tg * 2];
                uint32_t bh1 = *(const uint32_t*)&Bsh[n * SROW + k0 + 8 + tg * 2];
                uint32_t bl0 = *(const uint32_t*)&Bsl[n * SROW + k0     + tg * 2];
                uint32_t bl1 = *(const uint32_t*)&Bsl[n * SROW + k0 + 8 + tg * 2];
#pragma unroll
                for (int mt = 0; mt < 2; mt++) {
                    MMA16816(acc[mt][nt], ah[mt], bh0, bh1);
                    MMA16816(acc[mt][nt], ah[mt], bl0, bl1);
                    MMA16816(acc[mt][nt], al[mt], bh0, bh1);
                }
            }
        }
        __syncthreads();
    }

#pragma unroll
    for (int mt = 0; mt < 2; mt++) {
#pragma unroll
        for (int nt = 0; nt < 8; nt++) {
            int col = bn + wn + nt * 8 + tg * 2;
            float bv0 = P.bias ? P.bias[col]     : 0.f;
            float bv1 = P.bias ? P.bias[col + 1] : 0.f;
#pragma unroll
            for (int h = 0; h < 2; h++) {
                int row = bm + wm + mt * 16 + g + h * 8;
                float v0 = acc[mt][nt][h * 2]     + bv0;
                float v1 = acc[mt][nt][h * 2 + 1] + bv1;
                if (TANH) { v0 = tanhf(v0); v1 = tanhf(v1); }
                if (WF32) {
                    float* cp = P.C + (long)z * P.sC + (long)row * P.ldc + col;
                    cp[0] = v0; cp[1] = v1;
                }
                if (WBF16) {
                    long o = (long)z * P.sHL + (long)row * P.ldhl + col;
                    __nv_bfloat16 h0 = __float2bfloat16(v0);
                    __nv_bfloat16 h1 = __float2bfloat16(v1);
                    P.Chi[o] = h0; P.Chi[o + 1] = h1;
                    P.Clo[o]     = __float2bfloat16(v0 - __bfloat162float(h0));
                    P.Clo[o + 1] = __float2bfloat16(v1 - __bfloat162float(h1));
                }
            }
        }
    }
}

// ---------------- persistent bidirectional LSTM (fp16 h, split-fp16 W, 2-pass) ----------------
__device__ __forceinline__ void gbar_arrive(int dir) {
    __threadfence();
    __syncthreads();
    if (threadIdx.x == 0) atomicAdd(&g_barA[dir * 8], 1u);
}
__device__ __forceinline__ void gbar_wait(int dir, unsigned bc) {
    if (threadIdx.x == 0) {
        unsigned target = bc * 64u;
        while (*((volatile unsigned*)&g_barA[dir * 8]) < target) { __nanosleep(32); }
        __threadfence();
    }
    __syncthreads();
}
__global__ void reset_kernel() { g_barA[0] = 0u; g_barA[8] = 0u; }

// smem layout (bytes): WS hi/lo [32][520] fp16, HS [64][520] fp16, SG [64][33] fp32
#define LS_WS_H 0
#define LS_WS_L 33280
#define LS_HS   66560
#define LS_SG   133120
#define LSTM_SMEM (133120 + 64*33*4)

// stage one K-chunk (128 k) of fp16 h into smem
__device__ __forceinline__ void lstm_stage_chunk(
    const __half* Hp, uint32_t sbase, int ch, int tid)
{
    for (int c2 = tid; c2 < 1024; c2 += 256) {
        int row = c2 >> 4;
        int seg = (c2 & 15) + ch * 16;
        cpasync16(sbase + LS_HS + row * 1040 + seg * 16, Hp + row * H_ + seg * 8);
    }
    cpcommit();
}

// 128 blocks = 2 dirs x 64. Block owns 8 hidden units (32 gate-cols) over full K=512.
__global__ void __launch_bounds__(256, 1) lstm_kernel(
    const float* __restrict__ whf, const float* __restrict__ whb)
{
    extern __shared__ __align__(16) char smem[];
    __half* WS_h = (__half*)(smem + LS_WS_H);
    __half* WS_l = (__half*)(smem + LS_WS_L);
    __half* HS   = (__half*)(smem + LS_HS);
    float* SG = (float*)(smem + LS_SG);          // [64][33] gate sums
    const uint32_t sbase = smem_u32_of(smem);

    const int tid = threadIdx.x, lane = tid & 31, wid = tid >> 5;
    const int g = lane >> 2, tg = lane & 3;
    const int bid = blockIdx.x;
    const int dir = bid >> 6, b64 = bid & 63;
    const float* W    = dir ? whb : whf;           // [2048][512]
    const float* xpre = dir ? g_xpre_b : g_xpre_f;

    // preload W slice: rows r = gate*8 + j  (gate-col = gate*512 + b64*8 + j), split fp16
    for (int idx = tid; idx < 32 * 512; idx += 256) {
        int r = idx >> 9, k = idx & 511;
        int gg = r >> 3, j = r & 7;
        float v = W[(long)(gg * H_ + b64 * 8 + j) * H_ + k];
        __half h = __float2half_rn(v);
        WS_h[r * 520 + k] = h;
        WS_l[r * 520 + k] = __float2half_rn(v - __half2float(h));
    }
    __syncthreads();

    const int m0 = (wid & 3) * 16, n0 = (wid >> 2) * 16;   // 8 warps: 4m x 2n
    const int v0 = tid * 2;
    const int ub0 = v0 >> 3, uj0 = v0 & 7;
    const int col0 = b64 * 8 + uj0;
    float creg0 = 0.f, creg1 = 0.f;
    unsigned bc = 0;

    for (int s = 0; s < T_; s++) {
        int t = dir ? (T_ - 1 - s) : s;
        int wbuf = s & 1, rbuf = wbuf ^ 1;

        // prefetch xpre gates (independent of h) BEFORE the barrier wait
        float xg0[4], xg1[4];
        {
            const float* xp = xpre + ((long)ub0 * T_ + t) * G_ + b64 * 8 + uj0;
#pragma unroll
            for (int q = 0; q < 4; q++) { xg0[q] = __ldcg(&xp[q * H_]); xg1[q] = __ldcg(&xp[q * H_ + 1]); }
        }

        if (s > 0) {
            gbar_wait(dir, bc);   // all dir-peers finished step s-1 (h written + fenced)

            const __half* Hp = g_hfp[dir][rbuf];

            float acc[2][4];
#pragma unroll
            for (int nt = 0; nt < 2; nt++)
#pragma unroll
                for (int r = 0; r < 4; r++) acc[nt][r] = 0.f;

            // chunk-pipelined: stage chunk c+1 while MMA-ing chunk c
            lstm_stage_chunk(Hp, sbase, 0, tid);
#pragma unroll
            for (int chk = 0; chk < 4; chk++) {
                if (chk < 3) { lstm_stage_chunk(Hp, sbase, chk + 1, tid); cpwait<1>(); }
                else         { cpwait<0>(); }
                __syncthreads();

#pragma unroll
                for (int kss = 0; kss < 8; kss++) {
                    int kw = (chk * 8 + kss) * 16;
                    uint32_t ah[4];
                    ah[0] = *(const uint32_t*)&HS[(m0 + g    ) * 520 + kw     + tg * 2];
                    ah[1] = *(const uint32_t*)&HS[(m0 + g + 8) * 520 + kw     + tg * 2];
                    ah[2] = *(const uint32_t*)&HS[(m0 + g    ) * 520 + kw + 8 + tg * 2];
                    ah[3] = *(const uint32_t*)&HS[(m0 + g + 8) * 520 + kw + 8 + tg * 2];
#pragma unroll
                    for (int nt = 0; nt < 2; nt++) {
                        int n = n0 + nt * 8 + g;
                        uint32_t bh0 = *(const uint32_t*)&WS_h[n * 520 + kw     + tg * 2];
                        uint32_t bh1 = *(const uint32_t*)&WS_h[n * 520 + kw + 8 + tg * 2];
                        uint32_t bl0 = *(const uint32_t*)&WS_l[n * 520 + kw     + tg * 2];
                        uint32_t bl1 = *(const uint32_t*)&WS_l[n * 520 + kw + 8 + tg * 2];
                        MMAF16(acc[nt], ah, bh0, bh1);
                        MMAF16(acc[nt], ah, bl0, bl1);
                    }
                }
            }
#pragma unroll
            for (int nt = 0; nt < 2; nt++) {
                int col = n0 + nt * 8 + tg * 2;
                SG[(m0 + g    ) * 33 + col    ] = acc[nt][0];
                SG[(m0 + g    ) * 33 + col + 1] = acc[nt][1];
                SG[(m0 + g + 8) * 33 + col    ] = acc[nt][2];
                SG[(m0 + g + 8) * 33 + col + 1] = acc[nt][3];
            }
            __syncthreads();
        }

        // cell update (2 values per thread)
        {
            float gv0[4], gv1[4];
#pragma unroll
            for (int q = 0; q < 4; q++) {
                float a0 = xg0[q], a1 = xg1[q];
                if (s > 0) {
                    a0 += SG[ub0 * 33 + q * 8 + uj0];
                    a1 += SG[ub0 * 33 + q * 8 + uj0 + 1];
                }
                gv0[q] = a0; gv1[q] = a1;
            }
            float i0 = 1.f / (1.f + expf(-gv0[0]));
            float f0 = 1.f / (1.f + expf(-gv0[1]));
            float c0 = tanhf(gv0[2]);
            float o0 = 1.f / (1.f + expf(-gv0[3]));
            creg0 = f0 * creg0 + i0 * c0;
            float h0 = o0 * tanhf(creg0);

            float i1 = 1.f / (1.f + expf(-gv1[0]));
            float f1 = 1.f / (1.f + expf(-gv1[1]));
            float c1 = tanhf(gv1[2]);
            float o1 = 1.f / (1.f + expf(-gv1[3]));
            creg1 = f1 * creg1 + i1 * c1;
            float h1 = o1 * tanhf(creg1);

            long co = ((long)ub0 * T_ + t) * D_ + dir * H_ + col0;
            __nv_bfloat16 hh0 = __float2bfloat16(h0);
            __nv_bfloat16 hh1 = __float2bfloat16(h1);
            g_ctx[co]     = h0;
            g_ctx[co + 1] = h1;
            g_ch[co] = hh0; g_ch[co + 1] = hh1;     // ctx split emitted in-scan (from fp32 h)
            g_cl[co]     = __float2bfloat16(h0 - __bfloat162float(hh0));
            g_cl[co + 1] = __float2bfloat16(h1 - __bfloat162float(hh1));
            __half* Hp = g_hfp[dir][wbuf];
            Hp[ub0 * H_ + col0]     = __float2half_rn(h0);
            Hp[ub0 * H_ + col0 + 1] = __float2half_rn(h1);
        }
        gbar_arrive(dir); ++bc;
    }
}

// ---------------- softmax (fused attn hi/lo emit) / mean / head / bn ----------------
__global__ void softmax_kernel(const unsigned char* __restrict__ mask) {
    int row = blockIdx.x;
    int tid = threadIdx.x;
    int b = row >> 8;
    float v = g_scores[(long)row * T_ + tid];
    if (mask[b * T_ + tid]) v = -INFINITY;
    __shared__ float red[256];
    red[tid] = v; __syncthreads();
    for (int s = 128; s > 0; s >>= 1) {
        if (tid < s) red[tid] = fmaxf(red[tid], red[tid + s]);
        __syncthreads();
    }
    float m = red[0]; __syncthreads();
    float e = __expf(v - m);
    red[tid] = e; __syncthreads();
    for (int s = 128; s > 0; s >>= 1) {
        if (tid < s) red[tid] += red[tid + s];
        __syncthreads();
    }
    float a = e / red[0];
    long o = (long)row * T_ + tid;
    __nv_bfloat16 h = __float2bfloat16(a);
    g_ah[o] = h;
    g_al[o] = __float2bfloat16(a - __bfloat162float(h));
}

__global__ void mean_kernel() {
    int idx = blockIdx.x * 256 + threadIdx.x;
    int b = idx >> 10, d = idx & 1023;
    const float* p = &g_htilde[(long)b * T_ * D_ + d];
    float s = 0.f;
    for (int t = 0; t < T_; t++) s += p[(long)t * D_];
    g_ctxout[idx] = s * (1.0f / T_);
}

__global__ void yhead_kernel(const float* __restrict__ w_out, const float* __restrict__ b_out) {
    int m = blockIdx.x, tid = threadIdx.x;
    int wid = tid >> 5, lid = tid & 31;
    const float* x = &g_ctxout[m * D_];
    for (int n = wid; n < OUT_; n += 8) {
        const float* w = &w_out[(long)n * D_];
        float s = 0.f;
        for (int k = lid; k < D_; k += 32) s += x[k] * w[k];
#pragma unroll
        for (int o = 16; o > 0; o >>= 1) s += __shfl_down_sync(0xffffffffu, s, o);
        if (lid == 0) g_y[m * OUT_ + n] = tanhf(s + b_out[n]);
    }
}

__global__ void bn_kernel(const float* __restrict__ gamma, const float* __restrict__ beta,
                          float* __restrict__ out) {
    int n = threadIdx.x;
    float mu = 0.f;
    for (int b = 0; b < B_; b++) mu += g_y[b * OUT_ + n];
    mu *= (1.0f / B_);
    float var = 0.f;
    for (int b = 0; b < B_; b++) { float d = g_y[b * OUT_ + n] - mu; var += d * d; }
    var *= (1.0f / B_);
    float inv = rsqrtf(var + 1e-5f);
    float ga = gamma[n], be = beta[n];
    for (int b = 0; b < B_; b++)
        out[b * OUT_ + n] = ga * (g_y[b * OUT_ + n] - mu) * inv + be;
}

// ---------------- host launcher ----------------
extern "C" void kernel_launch(void* const* d_in, const int* in_sizes, int n_in,
                              void* d_out, int out_size) {
    const int*   inputs = (const int*)d_in[0];
    const unsigned char* mask = (const unsigned char*)d_in[1];
    const float* table  = (const float*)d_in[2];
    const float* w_ih_f = (const float*)d_in[3];
    const float* w_hh_f = (const float*)d_in[4];
    const float* b_ih_f = (const float*)d_in[5];
    const float* b_hh_f = (const float*)d_in[6];
    const float* w_ih_b = (const float*)d_in[7];
    const float* w_hh_b = (const float*)d_in[8];
    const float* b_ih_b = (const float*)d_in[9];
    const float* b_hh_b = (const float*)d_in[10];
    const float* w_in   = (const float*)d_in[11];
    const float* w_attn = (const float*)d_in[12];
    const float* w_out  = (const float*)d_in[13];
    const float* b_out  = (const float*)d_in[14];
    const float* gamma  = (const float*)d_in[15];
    const float* beta   = (const float*)d_in[16];
    float* out = (float*)d_out;

    float *xf, *xb, *ctx, *scores, *htilde, *bsf, *bsb;
    cudaGetSymbolAddress((void**)&xf,     g_xpre_f);
    cudaGetSymbolAddress((void**)&xb,     g_xpre_b);
    cudaGetSymbolAddress((void**)&ctx,    g_ctx);
    cudaGetSymbolAddress((void**)&scores, g_scores);
    cudaGetSymbolAddress((void**)&htilde, g_htilde);
    cudaGetSymbolAddress((void**)&bsf,    g_bsum_f);
    cudaGetSymbolAddress((void**)&bsb,    g_bsum_b);
    __nv_bfloat16 *eh,*el,*wfh,*wfl,*wbh,*wbl,*ch,*cl,*cth,*ctl,*winh,*winl,
                  *th,*tl,*ah,*al,*w1h,*w1l,*w2h,*w2l,*wh,*wl;
    cudaGetSymbolAddress((void**)&eh, g_eh);   cudaGetSymbolAddress((void**)&el, g_el);
    cudaGetSymbolAddress((void**)&wfh, g_wfh); cudaGetSymbolAddress((void**)&wfl, g_wfl);
    cudaGetSymbolAddress((void**)&wbh, g_wbh); cudaGetSymbolAddress((void**)&wbl, g_wbl);
    cudaGetSymbolAddress((void**)&ch, g_ch);   cudaGetSymbolAddress((void**)&cl, g_cl);
    cudaGetSymbolAddress((void**)&cth, g_cth); cudaGetSymbolAddress((void**)&ctl, g_ctl);
    cudaGetSymbolAddress((void**)&winh, g_winh); cudaGetSymbolAddress((void**)&winl, g_winl);
    cudaGetSymbolAddress((void**)&th, g_th);   cudaGetSymbolAddress((void**)&tl, g_tl);
    cudaGetSymbolAddress((void**)&ah, g_ah);   cudaGetSymbolAddress((void**)&al, g_al);
    cudaGetSymbolAddress((void**)&w1h, g_w1h); cudaGetSymbolAddress((void**)&w1l, g_w1l);
    cudaGetSymbolAddress((void**)&w2h, g_w2h); cudaGetSymbolAddress((void**)&w2l, g_w2l);
    cudaGetSymbolAddress((void**)&wh, g_wh);   cudaGetSymbolAddress((void**)&wl, g_wl);

    cudaFuncSetAttribute(mma_gemm_kernel<false,true,false>,
                         cudaFuncAttributeMaxDynamicSharedMemorySize, GEMM_SMEM);
    cudaFuncSetAttribute(mma_gemm_kernel<false,false,true>,
                         cudaFuncAttributeMaxDynamicSharedMemorySize, GEMM_SMEM);
    cudaFuncSetAttribute(mma_gemm_kernel<true,true,false>,
                         cudaFuncAttributeMaxDynamicSharedMemorySize, GEMM_SMEM);
    cudaFuncSetAttribute(lstm_kernel, cudaFuncAttributeMaxDynamicSharedMemorySize, LSTM_SMEM);

    // 0. embed
    embed_kernel<<<(BT_*E_ + 255) / 256, 256>>>(inputs, table);

    // 1. fused pre-LSTM conversions (embeds, w_ih_f, w_ih_b, bias sums)
    {
        long tot = (long)BT_*EP_ + 2L*G_*EP_ + G_;
        preconv_kernel<<<(unsigned)((tot + 255) / 256), 256>>>(
            w_ih_f, w_ih_b, b_ih_f, b_hh_f, b_ih_b, b_hh_b);
    }

    // 2-3. xpre = embeds @ w_ih^T + (b_ih + b_hh)
    {
        GemmP P{};
        P.nt = 1; P.K[0] = EP_; P.lda[0] = EP_; P.ldb[0] = EP_;
        P.Ah[0] = eh; P.Al[0] = el; P.ldc = G_;
        P.Bh[0] = wfh; P.Bl[0] = wfl; P.C = xf; P.bias = bsf;
        dim3 g(G_/128, BT_/128, 1);
        mma_gemm_kernel<false,true,false><<<g, 256, GEMM_SMEM>>>(P);
        P.Bh[0] = wbh; P.Bl[0] = wbl; P.C = xb; P.bias = bsb;
        mma_gemm_kernel<false,true,false><<<g, 256, GEMM_SMEM>>>(P);
    }

    // 4-5. persistent bidirectional LSTM (lstm at launch index 5 for ncu -s 5 -c 1)
    reset_kernel<<<1, 1>>>();
    lstm_kernel<<<NB_LSTM, 256, LSTM_SMEM>>>(w_hh_f, w_hh_b);

    // 6. fused post-LSTM weight conversions (w_in, w_attn halves)
    {
        long tot = 3L * D_ * D_;
        postconv_kernel<<<(unsigned)((tot + 255) / 256), 256>>>(w_in, w_attn);
    }

    // 7. ctx transposed split
    tconv_kernel<<<dim3(T_/32, D_/32, B_), dim3(32, 8)>>>(ctx, cth, ctl);

    // 8. target = ctx @ w_in^T  (bf16 hi/lo out)
    {
        GemmP P{};
        P.nt = 1; P.K[0] = D_; P.lda[0] = D_; P.ldb[0] = D_;
        P.Ah[0] = ch; P.Al[0] = cl; P.Bh[0] = winh; P.Bl[0] = winl;
        P.Chi = th; P.Clo = tl; P.ldhl = D_;
        dim3 g(D_/128, BT_/128, 1);
        mma_gemm_kernel<false,false,true><<<g, 256, GEMM_SMEM>>>(P);
    }

    // 9. scores[z] = target[z] @ ctx[z]^T  (fp32 out)
    {
        GemmP P{};
        P.nt = 1; P.K[0] = D_; P.lda[0] = D_; P.ldb[0] = D_;
        P.Ah[0] = th; P.Al[0] = tl; P.sA[0] = (long)T_*D_;
        P.Bh[0] = ch; P.Bl[0] = cl; P.sB[0] = (long)T_*D_;
        P.C = scores; P.ldc = T_; P.sC = (long)T_*T_;
        dim3 g(T_/128, T_/128, B_);
        mma_gemm_kernel<false,true,false><<<g, 256, GEMM_SMEM>>>(P);
    }

    // 10. softmax (emits attn bf16 hi/lo directly)
    softmax_kernel<<<BT_, 256>>>(mask);

    // 11. weighted[z] = attn[z] @ ctxT[z]^T  (bf16 hi/lo out)
    {
        GemmP P{};
        P.nt = 1; P.K[0] = T_; P.lda[0] = T_; P.ldb[0] = T_;
        P.Ah[0] = ah; P.Al[0] = al; P.sA[0] = (long)T_*T_;
        P.Bh[0] = cth; P.Bl[0] = ctl; P.sB[0] = (long)D_*T_;
        P.Chi = wh; P.Clo = wl; P.ldhl = D_; P.sHL = (long)T_*D_;
        dim3 g(D_/128, T_/128, B_);
        mma_gemm_kernel<false,false,true><<<g, 256, GEMM_SMEM>>>(P);
    }

    // 12. htilde = tanh(weighted @ W1^T + ctx @ W2^T)
    {
        GemmP P{};
        P.nt = 2;
        P.K[0] = D_; P.lda[0] = D_; P.ldb[0] = D_;
        P.Ah[0] = wh; P.Al[0] = wl; P.Bh[0] = w1h; P.Bl[0] = w1l;
        P.K[1] = D_; P.lda[1] = D_; P.ldb[1] = D_;
        P.Ah[1] = ch; P.Al[1] = cl; P.Bh[1] = w2h; P.Bl[1] = w2l;
        P.C = htilde; P.ldc = D_;
        dim3 g(D_/128, BT_/128, 1);
        mma_gemm_kernel<true,true,false><<<g, 256, GEMM_SMEM>>>(P);
    }

    // 13-15. mean, head, batchnorm
    mean_kernel<<<(B_*D_)/256, 256>>>();
    yhead_kernel<<<B_, 256>>>(w_out, b_out);
    bn_kernel<<<1, OUT_>>>(gamma, beta, out);
}